// round 5
// baseline (speedup 1.0000x reference)
#include <cuda_runtime.h>
#include <cstdint>

// Problem constants
#define Bn   8
#define En   16
#define CINn 64
#define Cn   64
#define HWn  4096
#define Tn   16      // pixels per conv block

// ---------------- scratch (device globals; no runtime allocation) ----------------
__device__ float g_value[(size_t)Bn * En * Cn * HWn];   // 134 MB V scratch
__device__ float g_dots[Bn * Cn * En * En];             // 512 KB gram matrices
__device__ float g_Wt[3 * CINn * Cn];                   // transposed weights [a][c]
__device__ float g_bias[3 * Cn];

// ---------------- f32x2 packed helpers (FFMA2: 2x fp32 MAC rate on sm_103a) -------
__device__ __forceinline__ unsigned long long fma2(unsigned long long a,
                                                   unsigned long long b,
                                                   unsigned long long c) {
    unsigned long long d;
    asm("fma.rn.f32x2 %0, %1, %2, %3;" : "=l"(d) : "l"(a), "l"(b), "l"(c));
    return d;
}
__device__ __forceinline__ unsigned long long pack2(float x) {
    unsigned long long d;
    unsigned int u = __float_as_uint(x);
    asm("mov.b64 %0, {%1, %2};" : "=l"(d) : "r"(u), "r"(u));
    return d;
}
__device__ __forceinline__ void unpack2(unsigned long long v, float& lo, float& hi) {
    unsigned int a, b;
    asm("mov.b64 {%0, %1}, %2;" : "=r"(a), "=r"(b) : "l"(v));
    lo = __uint_as_float(a);
    hi = __uint_as_float(b);
}

union F4U {
    float4 f;
    unsigned long long u[2];
};

__device__ __forceinline__ float selu_f(float x) {
    const float sc = 1.0507009873554805f;
    const float sa = 1.7580993408473766f;  // sc * alpha
    return x > 0.f ? sc * x : sa * (__expf(x) - 1.f);
}

// ---------------- kernel 0: weight transpose + bias copy ----------------
__global__ void prep_kernel(const float* __restrict__ Wv, const float* __restrict__ bv,
                            const float* __restrict__ Wk, const float* __restrict__ bk,
                            const float* __restrict__ Wq, const float* __restrict__ bq) {
    int conv = blockIdx.x;  // 0=V, 1=K, 2=Q
    const float* Ws = (conv == 0) ? Wv : (conv == 1) ? Wk : Wq;
    const float* bs = (conv == 0) ? bv : (conv == 1) ? bk : bq;
    int tid = threadIdx.x;
#pragma unroll
    for (int k = 0; k < 16; k++) {
        int idx = tid + k * 256;          // coalesced read of W[c][a]
        int c = idx >> 6, a = idx & 63;
        g_Wt[conv * 4096 + a * 64 + c] = Ws[idx];
    }
    if (tid < 64) g_bias[conv * 64 + tid] = bs[tid];
}

__global__ void zero_dots_kernel() {
    int i = blockIdx.x * blockDim.x + threadIdx.x;   // 128*256 = 32768 float4s
    ((float4*)g_dots)[i] = make_float4(0.f, 0.f, 0.f, 0.f);
}

// ---------------- kernel A: fused convs + partial gram accumulation ----------------
// smem layout (floats):
//   sX [16e][64a][16t]                         @ 0        (16384)
//   sK [16e] stride 1092 of [16t][68c]         @ 16384    (17472)
//   sQ same                                    @ 33856    (17472)
//   sW [64a][64c]                              @ 51328    (4096)
//   sb [64c]                                   @ 55424    (64)
#define ESTR   1092        // 16*68 + 4 : shifts banks across ensemble rows
#define SK_OFF 16384
#define SQ_OFF (SK_OFF + 16 * ESTR)
#define SW_OFF (SQ_OFF + 16 * ESTR)
#define SB_OFF (SW_OFF + 4096)
#define SMEM_FLOATS (SB_OFF + 64)   // 55488 floats = 221952 bytes

__global__ __launch_bounds__(256, 1) void conv_dots_kernel(const float* __restrict__ in) {
    extern __shared__ float sm[];
    const int tid = threadIdx.x;
    const int b = blockIdx.y;
    const int hw0 = blockIdx.x * Tn;

    // ---- load x tile: 4096 float4s, fully coalesced (64B-aligned rows) ----
    const float* xin = in + (size_t)b * (En * CINn * HWn);
    float4* sX4 = (float4*)sm;
#pragma unroll
    for (int k = 0; k < 16; k++) {
        int f = tid + k * 256;
        int row = f >> 2;          // e*64 + a
        int q = f & 3;
        sX4[f] = *(const float4*)(xin + (size_t)row * HWn + hw0 + q * 4);
    }

    // conv work decomposition: 4 ensemble members in parallel, 2c x 8t register tile
    const int eg = tid >> 6;          // 0..3
    const int cidx = (tid >> 1) & 31; // 0..31
    const int th = tid & 1;           // 0..1
    const int c0 = cidx * 2;
    const int t0 = th * 8;

    for (int conv = 0; conv < 3; conv++) {
        __syncthreads();  // prior conv done with sW
        {   // stage weights [a][c] + bias into smem
            float4* sW4 = (float4*)(sm + SW_OFF);
            const float4* gW4 = (const float4*)(g_Wt + conv * 4096);
#pragma unroll
            for (int k = 0; k < 4; k++) sW4[tid + k * 256] = gW4[tid + k * 256];
            if (tid < 64) sm[SB_OFF + tid] = g_bias[conv * 64 + tid];
        }
        __syncthreads();

        const float bia0 = sm[SB_OFF + c0];
        const float bia1 = sm[SB_OFF + c0 + 1];

        for (int eb = 0; eb < 4; eb++) {
            const int e = eb * 4 + eg;
            unsigned long long acc0[4], acc1[4];
            {
                unsigned long long p0 = pack2(bia0), p1 = pack2(bia1);
#pragma unroll
                for (int p = 0; p < 4; p++) { acc0[p] = p0; acc1[p] = p1; }
            }
            const float* xrow = sm + (e * 64) * 16 + t0;
            const float* wr = sm + SW_OFF + c0;

#pragma unroll 8
            for (int a = 0; a < 64; a++) {
                float2 w = *(const float2*)(wr + a * 64);
                unsigned long long w0 = pack2(w.x);
                unsigned long long w1 = pack2(w.y);
                F4U xa, xb;
                const float4* xf = (const float4*)(xrow + a * 16);
                xa.f = xf[0];
                xb.f = xf[1];
                acc0[0] = fma2(w0, xa.u[0], acc0[0]);
                acc0[1] = fma2(w0, xa.u[1], acc0[1]);
                acc0[2] = fma2(w0, xb.u[0], acc0[2]);
                acc0[3] = fma2(w0, xb.u[1], acc0[3]);
                acc1[0] = fma2(w1, xa.u[0], acc1[0]);
                acc1[1] = fma2(w1, xa.u[1], acc1[1]);
                acc1[2] = fma2(w1, xb.u[0], acc1[2]);
                acc1[3] = fma2(w1, xb.u[1], acc1[3]);
            }

            if (conv == 0) {
                // V: stream straight to global scratch (layout [b][e][c][hw])
                float* vout = g_value + ((size_t)(b * En + e) * Cn) * HWn + hw0 + t0;
                F4U r;
                r.u[0] = acc0[0]; r.u[1] = acc0[1];
                *(float4*)(vout + (size_t)c0 * HWn) = r.f;
                r.u[0] = acc0[2]; r.u[1] = acc0[3];
                *(float4*)(vout + (size_t)c0 * HWn + 4) = r.f;
                r.u[0] = acc1[0]; r.u[1] = acc1[1];
                *(float4*)(vout + (size_t)(c0 + 1) * HWn) = r.f;
                r.u[0] = acc1[2]; r.u[1] = acc1[3];
                *(float4*)(vout + (size_t)(c0 + 1) * HWn + 4) = r.f;
            } else {
                // K/Q: SELU then store to smem [e][t][c] (padded)
                float* sdst = sm + ((conv == 1) ? SK_OFF : SQ_OFF) + e * ESTR + c0;
#pragma unroll
                for (int p = 0; p < 4; p++) {
                    float l0, h0, l1, h1;
                    unpack2(acc0[p], l0, h0);
                    unpack2(acc1[p], l1, h1);
                    float2 v0 = make_float2(selu_f(l0), selu_f(l1));
                    float2 v1 = make_float2(selu_f(h0), selu_f(h1));
                    *(float2*)(sdst + (t0 + 2 * p) * 68) = v0;
                    *(float2*)(sdst + (t0 + 2 * p + 1) * 68) = v1;
                }
            }
        }
    }
    __syncthreads();

    // ---- partial gram: dots[b][c][i][j] += sum_t K[i,c,t]*Q[j,c,t] ----
    const int i = tid >> 4;
    const int j = tid & 15;
    const float* kb = sm + SK_OFF + i * ESTR;
    const float* qb = sm + SQ_OFF + j * ESTR;
    for (int cg = 0; cg < 16; cg++) {
        unsigned long long a0 = 0ull, a1 = 0ull;
        const float* kp = kb + cg * 4;
        const float* qp = qb + cg * 4;
#pragma unroll
        for (int t = 0; t < 16; t++) {
            F4U k4, q4;
            k4.f = *(const float4*)(kp + t * 68);
            q4.f = *(const float4*)(qp + t * 68);
            a0 = fma2(k4.u[0], q4.u[0], a0);
            a1 = fma2(k4.u[1], q4.u[1], a1);
        }
        float s0, s1, s2, s3;
        unpack2(a0, s0, s1);
        unpack2(a1, s2, s3);
        float* dp = g_dots + b * (Cn * En * En) + (cg * 4) * (En * En) + i * En + j;
        atomicAdd(dp,       s0);
        atomicAdd(dp + 256, s1);
        atomicAdd(dp + 512, s2);
        atomicAdd(dp + 768, s3);
    }
}

// ---------------- kernel C: softmax (per block, tiny) + weighted mix + SELU ----------
// mean-centering cancels: out[b,j,c,hw] = selu( sum_i softmax_i(dots)[i,j] * V[b,i,c,hw] )
__global__ __launch_bounds__(256) void apply_kernel(float* __restrict__ out) {
    __shared__ float sd[256];
    __shared__ float sw[256];
    const int tid = threadIdx.x;
    const int chunk = blockIdx.x;   // 0..3  (1024 pixels each)
    const int c = blockIdx.y;       // 0..63
    const int b = blockIdx.z;       // 0..7

    sd[tid] = g_dots[b * (Cn * En * En) + c * (En * En) + tid];
    __syncthreads();

    if (tid < 16) {   // softmax over i for column j = tid
        const int j = tid;
        float m = -1e30f;
#pragma unroll
        for (int i = 0; i < 16; i++) m = fmaxf(m, sd[i * 16 + j]);
        float e[16];
        float s = 0.f;
#pragma unroll
        for (int i = 0; i < 16; i++) {
            e[i] = __expf(sd[i * 16 + j] - m);
            s += e[i];
        }
        float inv = 1.f / s;
#pragma unroll
        for (int i = 0; i < 16; i++) sw[i * 16 + j] = e[i] * inv;
    }
    __syncthreads();

    const int pix = chunk * 1024 + tid * 4;
    const float* vbase = g_value + ((size_t)b * En * Cn + c) * HWn + pix;
    F4U v[16];
#pragma unroll
    for (int i = 0; i < 16; i++)
        v[i].f = *(const float4*)(vbase + (size_t)i * Cn * HWn);

    float* obase = out + ((size_t)b * En * Cn + c) * HWn + pix;
    for (int j = 0; j < 16; j++) {
        unsigned long long a0 = 0ull, a1 = 0ull;
#pragma unroll
        for (int i = 0; i < 16; i++) {
            unsigned long long wp = pack2(sw[i * 16 + j]);
            a0 = fma2(wp, v[i].u[0], a0);
            a1 = fma2(wp, v[i].u[1], a1);
        }
        float f0, f1, f2, f3;
        unpack2(a0, f0, f1);
        unpack2(a1, f2, f3);
        float4 o = make_float4(selu_f(f0), selu_f(f1), selu_f(f2), selu_f(f3));
        *(float4*)(obase + (size_t)j * Cn * HWn) = o;
    }
}

// ---------------- launcher ----------------
extern "C" void kernel_launch(void* const* d_in, const int* in_sizes, int n_in,
                              void* d_out, int out_size) {
    const float* in = (const float*)d_in[0];
    const float* Wv = (const float*)d_in[1];
    const float* bv = (const float*)d_in[2];
    const float* Wk = (const float*)d_in[3];
    const float* bk = (const float*)d_in[4];
    const float* Wq = (const float*)d_in[5];
    const float* bq = (const float*)d_in[6];
    float* out = (float*)d_out;

    cudaFuncSetAttribute(conv_dots_kernel,
                         cudaFuncAttributeMaxDynamicSharedMemorySize,
                         SMEM_FLOATS * (int)sizeof(float));

    prep_kernel<<<3, 256>>>(Wv, bv, Wk, bk, Wq, bq);
    zero_dots_kernel<<<128, 256>>>();
    conv_dots_kernel<<<dim3(HWn / Tn, Bn), 256, SMEM_FLOATS * sizeof(float)>>>(in);
    apply_kernel<<<dim3(4, Cn, Bn), 256>>>(out);
}

// round 8
// speedup vs baseline: 1.0372x; 1.0372x over previous
#include <cuda_runtime.h>
#include <cstdint>

// Problem constants
#define Bn    8
#define En    16
#define CINn  64
#define Cn    64
#define HWn   4096
#define Tn    16            // pixels per inner pass
#define MACRO 2             // passes per block (32 px per block)
#define HWB   (HWn / (Tn * MACRO))   // 128 macro-tiles per batch

// ---------------- scratch (device globals; no runtime allocation) ----------------
__device__ float g_value[(size_t)Bn * En * Cn * HWn];            // 134 MB V scratch
__device__ float g_dots[Bn * Cn * En * En];                      // 512 KB gram
__device__ float g_partial[(size_t)Bn * HWB * Cn * En * En];     // 67 MB partial gram
__device__ float g_Wt[3 * CINn * Cn];                            // transposed weights [a][c]
__device__ float g_bias[3 * Cn];

// ---------------- f32x2 packed helpers (FFMA2: 2x fp32 MAC rate) ----------------
__device__ __forceinline__ unsigned long long fma2(unsigned long long a,
                                                   unsigned long long b,
                                                   unsigned long long c) {
    unsigned long long d;
    asm("fma.rn.f32x2 %0, %1, %2, %3;" : "=l"(d) : "l"(a), "l"(b), "l"(c));
    return d;
}
__device__ __forceinline__ unsigned long long pack2(float x) {
    unsigned long long d;
    unsigned int u = __float_as_uint(x);
    asm("mov.b64 %0, {%1, %2};" : "=l"(d) : "r"(u), "r"(u));
    return d;
}
__device__ __forceinline__ void unpack2(unsigned long long v, float& lo, float& hi) {
    unsigned int a, b;
    asm("mov.b64 {%0, %1}, %2;" : "=r"(a), "=r"(b) : "l"(v));
    lo = __uint_as_float(a);
    hi = __uint_as_float(b);
}

union F4U {
    float4 f;
    unsigned long long u[2];
};

__device__ __forceinline__ float selu_f(float x) {
    const float sc = 1.0507009873554805f;
    const float sa = 1.7580993408473766f;  // sc * alpha
    return x > 0.f ? sc * x : sa * (__expf(x) - 1.f);
}

// ---------------- kernel 0: weight transpose + bias copy ----------------
__global__ void prep_kernel(const float* __restrict__ Wv, const float* __restrict__ bv,
                            const float* __restrict__ Wk, const float* __restrict__ bk,
                            const float* __restrict__ Wq, const float* __restrict__ bq) {
    int conv = blockIdx.x;  // 0=V, 1=K, 2=Q
    const float* Ws = (conv == 0) ? Wv : (conv == 1) ? Wk : Wq;
    const float* bs = (conv == 0) ? bv : (conv == 1) ? bk : bq;
    int tid = threadIdx.x;
#pragma unroll
    for (int k = 0; k < 16; k++) {
        int idx = tid + k * 256;          // coalesced read of W[c][a]
        int c = idx >> 6, a = idx & 63;
        g_Wt[conv * 4096 + a * 64 + c] = Ws[idx];
    }
    if (tid < 64) g_bias[conv * 64 + tid] = bs[tid];
}

// ---------------- kernel A: fused convs + register-resident partial gram ----------
// smem layout (floats):
//   sX [16e][64a][16t]                    @ 0        (16384)
//   sK [16e] stride 1092 of [16t][68c]    @ 16384
//   sQ same                               @ 33856
//   sW [64a][64c]                         @ 51328
//   sb [64c]                              @ 55424
#define ESTR   1092
#define SK_OFF 16384
#define SQ_OFF (SK_OFF + 16 * ESTR)
#define SW_OFF (SQ_OFF + 16 * ESTR)
#define SB_OFF (SW_OFF + 4096)
#define SMEM_FLOATS (SB_OFF + 64)   // 55488 floats = 221952 bytes

__global__ __launch_bounds__(512, 1) void conv_dots_kernel(const float* __restrict__ in) {
    extern __shared__ float sm[];
    const int tid = threadIdx.x;
    const int b = blockIdx.y;
    const int hwb = blockIdx.x;          // macro-tile index, 0..127

    // ---- gram thread mapping: thread = (i, j pair, cg quarter) ----
    const int gp  = tid & 127;
    const int gi  = gp >> 3;             // 0..15
    const int gj0 = (gp & 7) * 2;        // 0,2,..,14
    const int gq  = tid >> 7;            // 0..3  (channel quarter)
    unsigned long long gacc[16];         // [cc][j in 2][c-pair in 2], persistent
#pragma unroll
    for (int z = 0; z < 16; z++) gacc[z] = 0ull;

    // ---- conv thread mapping: all 16 e in parallel, 4c x 8t per thread ----
    const int e  = tid >> 5;             // 0..15
    const int cq = (tid >> 1) & 15;      // c0 = 4*cq
    const int th = tid & 1;              // t0 = 8*th
    const int c0 = cq * 4;
    const int t0 = th * 8;

    const float* xin = in + (size_t)b * (En * CINn * HWn);

    for (int pass = 0; pass < MACRO; pass++) {
        const int hw0 = (hwb * MACRO + pass) * Tn;

        // ---- load x tile: 4096 float4s, coalesced (sX free: prior readers synced) ----
        float4* sX4 = (float4*)sm;
#pragma unroll
        for (int k = 0; k < 8; k++) {
            int f = tid + k * 512;
            int row = f >> 2;            // e*64 + a
            int q = f & 3;
            sX4[f] = *(const float4*)(xin + (size_t)row * HWn + hw0 + q * 4);
        }

        for (int conv = 0; conv < 3; conv++) {
            __syncthreads();  // X loaded / prior conv done with sW and its outputs
            {   // stage weights [a][c] + bias
                float4* sW4 = (float4*)(sm + SW_OFF);
                const float4* gW4 = (const float4*)(g_Wt + conv * 4096);
                sW4[tid] = gW4[tid];
                sW4[tid + 512] = gW4[tid + 512];
                if (tid < 64) sm[SB_OFF + tid] = g_bias[conv * 64 + tid];
            }
            __syncthreads();

            unsigned long long acc[4][4];   // [c][t-pair]
            {
                const float4 b4 = *(const float4*)(sm + SB_OFF + c0);
                unsigned long long p0 = pack2(b4.x), p1 = pack2(b4.y);
                unsigned long long p2 = pack2(b4.z), p3 = pack2(b4.w);
#pragma unroll
                for (int p = 0; p < 4; p++) {
                    acc[0][p] = p0; acc[1][p] = p1; acc[2][p] = p2; acc[3][p] = p3;
                }
            }
            const float* xrow = sm + (e * 64) * 16 + t0;
            const float* wr = sm + SW_OFF + c0;

#pragma unroll 8
            for (int a = 0; a < 64; a++) {
                float4 w4 = *(const float4*)(wr + a * 64);
                unsigned long long wp[4] = {pack2(w4.x), pack2(w4.y),
                                            pack2(w4.z), pack2(w4.w)};
                F4U xa, xb;
                const float4* xf = (const float4*)(xrow + a * 16);
                xa.f = xf[0];
                xb.f = xf[1];
                unsigned long long xp[4] = {xa.u[0], xa.u[1], xb.u[0], xb.u[1]};
#pragma unroll
                for (int c = 0; c < 4; c++)
#pragma unroll
                    for (int p = 0; p < 4; p++)
                        acc[c][p] = fma2(wp[c], xp[p], acc[c][p]);
            }

            if (conv == 0) {
                // V -> global scratch [b][e][c][hw]
                float* vout = g_value + ((size_t)(b * En + e) * Cn + c0) * HWn + hw0 + t0;
#pragma unroll
                for (int c = 0; c < 4; c++) {
                    F4U r;
                    r.u[0] = acc[c][0]; r.u[1] = acc[c][1];
                    *(float4*)(vout + (size_t)c * HWn) = r.f;
                    r.u[0] = acc[c][2]; r.u[1] = acc[c][3];
                    *(float4*)(vout + (size_t)c * HWn + 4) = r.f;
                }
            } else {
                // K/Q: SELU then smem [e][t][c] (padded)
                float* sdst = sm + ((conv == 1) ? SK_OFF : SQ_OFF) + e * ESTR + c0;
#pragma unroll
                for (int p = 0; p < 4; p++) {
                    float lo[4], hi[4];
#pragma unroll
                    for (int c = 0; c < 4; c++) unpack2(acc[c][p], lo[c], hi[c]);
                    float4 vlo = make_float4(selu_f(lo[0]), selu_f(lo[1]),
                                             selu_f(lo[2]), selu_f(lo[3]));
                    float4 vhi = make_float4(selu_f(hi[0]), selu_f(hi[1]),
                                             selu_f(hi[2]), selu_f(hi[3]));
                    *(float4*)(sdst + (t0 + 2 * p) * 68) = vlo;
                    *(float4*)(sdst + (t0 + 2 * p + 1) * 68) = vhi;
                }
            }
        }
        __syncthreads();   // K,Q complete

        // ---- gram accumulate into persistent registers ----
        {
            const float* kb = sm + SK_OFF + gi * ESTR;
            const float* qa = sm + SQ_OFF + gj0 * ESTR;
            const float* qb = sm + SQ_OFF + (gj0 + 1) * ESTR;
#pragma unroll
            for (int cc = 0; cc < 4; cc++) {
                const int coff = (gq * 4 + cc) * 4;
                unsigned long long* ga = gacc + cc * 4;
#pragma unroll
                for (int t = 0; t < 16; t++) {
                    F4U k4, q4a, q4b;
                    k4.f  = *(const float4*)(kb + t * 68 + coff);
                    q4a.f = *(const float4*)(qa + t * 68 + coff);
                    q4b.f = *(const float4*)(qb + t * 68 + coff);
                    ga[0] = fma2(k4.u[0], q4a.u[0], ga[0]);
                    ga[1] = fma2(k4.u[1], q4a.u[1], ga[1]);
                    ga[2] = fma2(k4.u[0], q4b.u[0], ga[2]);
                    ga[3] = fma2(k4.u[1], q4b.u[1], ga[3]);
                }
            }
        }
        __syncthreads();   // gram reads done before next pass overwrites sK/sQ & sX users
    }

    // ---- write partial gram (no atomics): p[b][hwb][c][i][j] ----
    {
        float* pb = g_partial + ((size_t)(b * HWB + hwb) * Cn) * 256 + gi * 16 + gj0;
#pragma unroll
        for (int cc = 0; cc < 4; cc++) {
#pragma unroll
            for (int cp = 0; cp < 2; cp++) {
                float j0lo, j0hi, j1lo, j1hi;
                unpack2(gacc[cc * 4 + cp],     j0lo, j0hi);   // j=gj0,   c even/odd
                unpack2(gacc[cc * 4 + 2 + cp], j1lo, j1hi);   // j=gj0+1
                int ce = (gq * 4 + cc) * 4 + cp * 2;
                float2 v0 = make_float2(j0lo, j1lo);
                float2 v1 = make_float2(j0hi, j1hi);
                *(float2*)(pb + (size_t)ce * 256) = v0;
                *(float2*)(pb + (size_t)(ce + 1) * 256) = v1;
            }
        }
    }
}

// ---------------- kernel B: reduce partial grams -> g_dots ----------------
__global__ __launch_bounds__(256) void reduce_dots_kernel() {
    const int bc = blockIdx.x;           // b*64 + c
    const int tid = threadIdx.x;         // i*16 + j
    const int b = bc >> 6, c = bc & 63;
    const float* p = g_partial + ((size_t)(b * HWB) * Cn + c) * 256 + tid;
    const size_t str = (size_t)Cn * 256;
    float s0 = 0.f, s1 = 0.f, s2 = 0.f, s3 = 0.f;
    for (int h = 0; h < HWB; h += 4) {
        s0 += p[(size_t)(h + 0) * str];
        s1 += p[(size_t)(h + 1) * str];
        s2 += p[(size_t)(h + 2) * str];
        s3 += p[(size_t)(h + 3) * str];
    }
    g_dots[bc * 256 + tid] = (s0 + s1) + (s2 + s3);
}

// ---------------- kernel C: softmax + weighted mix + SELU ----------------
// mean-centering cancels: out[b,j,c,hw] = selu( sum_i softmax_i(dots)[i,j] * V[b,i,c,hw] )
__global__ __launch_bounds__(256) void apply_kernel(float* __restrict__ out) {
    __shared__ float sd[256];
    __shared__ float sw[256];
    const int tid = threadIdx.x;
    const int chunk = blockIdx.x;   // 0..3  (1024 pixels each)
    const int c = blockIdx.y;       // 0..63
    const int b = blockIdx.z;       // 0..7

    sd[tid] = g_dots[b * (Cn * En * En) + c * (En * En) + tid];
    __syncthreads();

    if (tid < 16) {   // softmax over i for column j = tid
        const int j = tid;
        float m = -1e30f;
#pragma unroll
        for (int i = 0; i < 16; i++) m = fmaxf(m, sd[i * 16 + j]);
        float e[16];
        float s = 0.f;
#pragma unroll
        for (int i = 0; i < 16; i++) {
            e[i] = __expf(sd[i * 16 + j] - m);
            s += e[i];
        }
        float inv = 1.f / s;
#pragma unroll
        for (int i = 0; i < 16; i++) sw[i * 16 + j] = e[i] * inv;
    }
    __syncthreads();

    const int pix = chunk * 1024 + tid * 4;
    const float* vbase = g_value + ((size_t)b * En * Cn + c) * HWn + pix;
    F4U v[16];
#pragma unroll
    for (int i = 0; i < 16; i++)
        v[i].f = *(const float4*)(vbase + (size_t)i * Cn * HWn);

    float* obase = out + ((size_t)b * En * Cn + c) * HWn + pix;
    for (int j = 0; j < 16; j++) {
        unsigned long long a0 = 0ull, a1 = 0ull;
#pragma unroll
        for (int i = 0; i < 16; i++) {
            unsigned long long wp = pack2(sw[i * 16 + j]);
            a0 = fma2(wp, v[i].u[0], a0);
            a1 = fma2(wp, v[i].u[1], a1);
        }
        float f0, f1, f2, f3;
        unpack2(a0, f0, f1);
        unpack2(a1, f2, f3);
        float4 o = make_float4(selu_f(f0), selu_f(f1), selu_f(f2), selu_f(f3));
        *(float4*)(obase + (size_t)j * Cn * HWn) = o;
    }
}

// ---------------- launcher ----------------
extern "C" void kernel_launch(void* const* d_in, const int* in_sizes, int n_in,
                              void* d_out, int out_size) {
    const float* in = (const float*)d_in[0];
    const float* Wv = (const float*)d_in[1];
    const float* bv = (const float*)d_in[2];
    const float* Wk = (const float*)d_in[3];
    const float* bk = (const float*)d_in[4];
    const float* Wq = (const float*)d_in[5];
    const float* bq = (const float*)d_in[6];
    float* out = (float*)d_out;

    cudaFuncSetAttribute(conv_dots_kernel,
                         cudaFuncAttributeMaxDynamicSharedMemorySize,
                         SMEM_FLOATS * (int)sizeof(float));

    prep_kernel<<<3, 256>>>(Wv, bv, Wk, bk, Wq, bq);
    conv_dots_kernel<<<dim3(HWB, Bn), 512, SMEM_FLOATS * sizeof(float)>>>(in);
    reduce_dots_kernel<<<Bn * Cn, 256>>>();
    apply_kernel<<<dim3(4, Cn, Bn), 256>>>(out);
}

// round 10
// speedup vs baseline: 1.2485x; 1.2037x over previous
#include <cuda_runtime.h>
#include <cuda_bf16.h>
#include <cstdint>

// Problem constants
#define Bn   8
#define En   16
#define CINn 64
#define Cn   64
#define HWn  4096

// ---------------- scratch (device globals; no runtime allocation) ----------------
__device__ float g_value[(size_t)Bn * En * Cn * HWn];   // 134 MB
__device__ float g_K[(size_t)Bn * En * Cn * HWn];       // 134 MB
__device__ float g_Q[(size_t)Bn * En * Cn * HWn];       // 134 MB
__device__ float g_dots[Bn * Cn * En * En];             // 512 KB
__device__ __align__(16) __nv_bfloat16 g_Wh[192 * 64];  // stacked V,K,Q weights hi
__device__ __align__(16) __nv_bfloat16 g_Wl[192 * 64];  // lo
__device__ float g_biasA[192];

// ---------------- small helpers ----------------
__device__ __forceinline__ unsigned long long fma2(unsigned long long a,
                                                   unsigned long long b,
                                                   unsigned long long c) {
    unsigned long long d;
    asm("fma.rn.f32x2 %0, %1, %2, %3;" : "=l"(d) : "l"(a), "l"(b), "l"(c));
    return d;
}
__device__ __forceinline__ unsigned long long pack2(float x) {
    unsigned long long d;
    unsigned int u = __float_as_uint(x);
    asm("mov.b64 %0, {%1, %2};" : "=l"(d) : "r"(u), "r"(u));
    return d;
}
__device__ __forceinline__ void unpack2(unsigned long long v, float& lo, float& hi) {
    unsigned int a, b;
    asm("mov.b64 {%0, %1}, %2;" : "=r"(a), "=r"(b) : "l"(v));
    lo = __uint_as_float(a);
    hi = __uint_as_float(b);
}
union F4U {
    float4 f;
    unsigned long long u[2];
};
__device__ __forceinline__ float selu_f(float x) {
    const float sc = 1.0507009873554805f;
    const float sa = 1.7580993408473766f;  // sc * alpha
    return x > 0.f ? sc * x : sa * (__expf(x) - 1.f);
}
__device__ __forceinline__ uint32_t smem_u32(const void* p) {
    uint32_t a;
    asm("{ .reg .u64 t; cvta.to.shared.u64 t, %1; cvt.u32.u64 %0, t; }" : "=r"(a) : "l"(p));
    return a;
}

// ---------------- portable tensor-core primitives (sm_80+ PTX, works on compute_103) ----
__device__ __forceinline__ void ldm_x4(uint32_t& a0, uint32_t& a1, uint32_t& a2,
                                       uint32_t& a3, uint32_t addr) {
    asm volatile("ldmatrix.sync.aligned.m8n8.x4.shared.b16 {%0,%1,%2,%3}, [%4];"
                 : "=r"(a0), "=r"(a1), "=r"(a2), "=r"(a3) : "r"(addr));
}
__device__ __forceinline__ void ldm_x2(uint32_t& b0, uint32_t& b1, uint32_t addr) {
    asm volatile("ldmatrix.sync.aligned.m8n8.x2.shared.b16 {%0,%1}, [%2];"
                 : "=r"(b0), "=r"(b1) : "r"(addr));
}
__device__ __forceinline__ void mma_bf16(float* d, uint32_t a0, uint32_t a1,
                                         uint32_t a2, uint32_t a3,
                                         uint32_t b0, uint32_t b1) {
    asm volatile(
        "mma.sync.aligned.m16n8k16.row.col.f32.bf16.bf16.f32 "
        "{%0,%1,%2,%3}, {%4,%5,%6,%7}, {%8,%9}, {%0,%1,%2,%3};"
        : "+f"(d[0]), "+f"(d[1]), "+f"(d[2]), "+f"(d[3])
        : "r"(a0), "r"(a1), "r"(a2), "r"(a3), "r"(b0), "r"(b1));
}

// ---------------- kernel 0: weight split to bf16 hi/lo + bias ----------------
__global__ void prep_kernel(const float* __restrict__ Wv, const float* __restrict__ bv,
                            const float* __restrict__ Wk, const float* __restrict__ bk,
                            const float* __restrict__ Wq, const float* __restrict__ bq) {
    int r = threadIdx.x;  // 0..191
    const float* Ws = (r < 64) ? Wv : (r < 128) ? Wk : Wq;
    const float* bs = (r < 64) ? bv : (r < 128) ? bk : bq;
    int rr = r & 63;
    for (int a = 0; a < 64; a++) {
        float w = Ws[rr * 64 + a];
        __nv_bfloat16 hi = __float2bfloat16(w);
        __nv_bfloat16 lo = __float2bfloat16(w - __bfloat162float(hi));
        g_Wh[r * 64 + a] = hi;
        g_Wl[r * 64 + a] = lo;
    }
    g_biasA[r] = bs[rr];
}

// ---------------- kernel A: warp-MMA 1x1 convs (V,K,Q) ----------------
// Per block: one (b,e), 128-pixel tile. GEMM M=128 px, N=192 outs, K=64.
// 3x-bf16 precision split (hi*hi + lo*hi + hi*lo), fp32 accumulators.
//
// smem byte layout:
//   A_hi [128 px][72 a] bf16   @ 0       (18432)
//   A_lo                       @ 18432   (18432)
//   B_hi [192 n][72 a] bf16    @ 36864   (27648)
//   B_lo                       @ 64512   (27648)
//   bias [192] f32             @ 92160   (768)
//   (fp32 transpose bounce [64 a][132 px] overlaps B region @ 36864, 33792 B)
#define SM_AH   0
#define SM_AL   18432
#define SM_BH   36864
#define SM_BL   64512
#define SM_BIAS 92160
#define SM_A_TOTAL (92160 + 768)
#define ASTR 144           // bytes per A/B smem row (72 bf16)

__global__ __launch_bounds__(512, 1) void conv_tc_kernel(const float* __restrict__ in) {
    extern __shared__ char smem[];
    const uint32_t sb = smem_u32(smem);
    const int tid = threadIdx.x;
    const int w = tid >> 5;
    const int lane = tid & 31;
    const int px0 = blockIdx.x * 128;
    const int e = blockIdx.y;
    const int b = blockIdx.z;

    // ---- stage 1: coalesced X load -> fp32 bounce [64 a][132 px] ----
    {
        const float* xb = in + ((size_t)(b * En + e) * CINn) * HWn + px0;
        float* sT = (float*)(smem + SM_BH);
#pragma unroll
        for (int k = 0; k < 4; k++) {
            int idx = tid + k * 512;        // 0..2047
            int a = idx >> 5;
            int p4 = idx & 31;
            float4 v = *(const float4*)(xb + (size_t)a * HWn + p4 * 4);
            *(float4*)(sT + a * 132 + p4 * 4) = v;
        }
    }
    // bias while loads land
    if (tid < 192) ((float*)(smem + SM_BIAS))[tid] = g_biasA[tid];
    __syncthreads();

    // ---- stage 2: transpose + bf16 hi/lo split -> A tiles [px][72] ----
    {
        const float* sT = (const float*)(smem + SM_BH);
        const int px = tid & 127;
        const int a0g = (tid >> 7) * 16;     // 4 groups of 16 a
#pragma unroll
        for (int q2 = 0; q2 < 2; q2++) {
            int a0 = a0g + q2 * 8;
            union { uint4 u; __nv_bfloat16 h[8]; } hi, lo;
#pragma unroll
            for (int q = 0; q < 8; q++) {
                float x = sT[(a0 + q) * 132 + px];
                __nv_bfloat16 h = __float2bfloat16(x);
                hi.h[q] = h;
                lo.h[q] = __float2bfloat16(x - __bfloat162float(h));
            }
            *(uint4*)(smem + SM_AH + px * ASTR + a0 * 2) = hi.u;
            *(uint4*)(smem + SM_AL + px * ASTR + a0 * 2) = lo.u;
        }
    }
    __syncthreads();   // bounce dead; load weights over it

    // ---- stage 3: weights -> smem [192 n][72 a] bf16 hi/lo ----
    {
        const uint4* wh = (const uint4*)g_Wh;
        const uint4* wl = (const uint4*)g_Wl;
#pragma unroll
        for (int k = 0; k < 3; k++) {
            int idx = tid + k * 512;        // 0..1535 (16B chunks; 8 per 64-elem row)
            int row = idx >> 3;
            int c16 = idx & 7;
            uint32_t dst = row * ASTR + c16 * 16;
            *(uint4*)(smem + SM_BH + dst) = wh[idx];
            *(uint4*)(smem + SM_BL + dst) = wl[idx];
        }
    }
    __syncthreads();

    // ---- MMA: warp = 16 px strip x 96-output half ----
    const int m0 = (w & 7) * 16;
    const int nh = (w >> 3) * 96;

    float acc[12][4];
#pragma unroll
    for (int t = 0; t < 12; t++)
#pragma unroll
        for (int r = 0; r < 4; r++) acc[t][r] = 0.f;

    // ldmatrix lane-address bases
    const uint32_t arow_base = (uint32_t)((m0 + (lane & 15)) * ASTR + (lane >> 4) * 16);
    const uint32_t brow_base = (uint32_t)((nh + (lane & 7)) * ASTR + ((lane >> 3) & 1) * 16);

#pragma unroll
    for (int pass = 0; pass < 3; pass++) {
        const uint32_t Abase = sb + ((pass == 1) ? SM_AL : SM_AH) + arow_base;
        const uint32_t Bbase = sb + ((pass == 2) ? SM_BL : SM_BH) + brow_base;
#pragma unroll
        for (int k = 0; k < 4; k++) {
            uint32_t a0, a1, a2, a3;
            ldm_x4(a0, a1, a2, a3, Abase + k * 32);
#pragma unroll
            for (int t = 0; t < 12; t++) {
                uint32_t b0, b1;
                ldm_x2(b0, b1, Bbase + k * 32 + t * (8 * ASTR));
                mma_bf16(acc[t], a0, a1, a2, a3, b0, b1);
            }
        }
    }

    // ---- epilogue: bias + SELU(K,Q) + direct stores ----
    {
        const float* sBias = (const float*)(smem + SM_BIAS);
        const int pxa = m0 + (lane >> 2);          // rows for d0,d1
        const size_t ebase = ((size_t)(b * En + e) * Cn) * HWn + px0;
#pragma unroll
        for (int t = 0; t < 12; t++) {
            const int n0 = nh + t * 8;
            const int c = n0 + (lane & 3) * 2;
            const bool do_selu = (n0 >= 64);
            float* base = (n0 < 64) ? g_value : (n0 < 128) ? g_K : g_Q;
            const int cc = c & 63;
            float v0 = acc[t][0] + sBias[c];
            float v1 = acc[t][1] + sBias[c + 1];
            float v2 = acc[t][2] + sBias[c];
            float v3 = acc[t][3] + sBias[c + 1];
            if (do_selu) {
                v0 = selu_f(v0); v1 = selu_f(v1);
                v2 = selu_f(v2); v3 = selu_f(v3);
            }
            float* p0 = base + ebase + (size_t)cc * HWn + pxa;
            float* p1 = base + ebase + (size_t)(cc + 1) * HWn + pxa;
            p0[0] = v0;
            p1[0] = v1;
            p0[8] = v2;
            p1[8] = v3;
        }
    }
}

// ---------------- kernel B: gram matrices ----------------
// dots[b,c,i,j] = sum_hw K[b,i,c,hw] * Q[b,j,c,hw]; one block per (b,c)
#define GCH 512
__global__ __launch_bounds__(256) void gram_kernel() {
    extern __shared__ float s[];   // sK [16][516], sQ [16][516]
    const int tid = threadIdx.x;
    const int b = blockIdx.x >> 6;
    const int c = blockIdx.x & 63;
    const int i = tid >> 4, j = tid & 15;
    float* sK = s;
    float* sQ = s + 16 * 516;

    unsigned long long a0 = 0ull, a1 = 0ull;
    for (int ch = 0; ch < HWn / GCH; ch++) {
        const int hw0 = ch * GCH;
        __syncthreads();
#pragma unroll
        for (int z = 0; z < 8; z++) {
            int idx = tid + z * 256;       // 0..2047
            int row = idx >> 7, f4 = idx & 127;
            size_t src = ((size_t)(b * En + row) * Cn + c) * HWn + hw0 + f4 * 4;
            *(float4*)(sK + row * 516 + f4 * 4) = *(const float4*)(g_K + src);
            *(float4*)(sQ + row * 516 + f4 * 4) = *(const float4*)(g_Q + src);
        }
        __syncthreads();
        const float* kr = sK + i * 516;
        const float* qr = sQ + j * 516;
#pragma unroll 8
        for (int t = 0; t < GCH; t += 4) {
            F4U k4, q4;
            k4.f = *(const float4*)(kr + t);
            q4.f = *(const float4*)(qr + t);
            a0 = fma2(k4.u[0], q4.u[0], a0);
            a1 = fma2(k4.u[1], q4.u[1], a1);
        }
    }
    float s0, s1, s2, s3;
    unpack2(a0, s0, s1);
    unpack2(a1, s2, s3);
    g_dots[blockIdx.x * 256 + tid] = (s0 + s1) + (s2 + s3);
}

// ---------------- kernel C: softmax + weighted mix + SELU ----------------
// mean-centering cancels: out[b,j,c,hw] = selu( sum_i softmax_i(dots)[i,j] * V[b,i,c,hw] )
__global__ __launch_bounds__(256) void apply_kernel(float* __restrict__ out) {
    __shared__ float sd[256];
    __shared__ float sw[256];
    const int tid = threadIdx.x;
    const int chunk = blockIdx.x;   // 0..3
    const int c = blockIdx.y;
    const int b = blockIdx.z;

    sd[tid] = g_dots[b * (Cn * En * En) + c * (En * En) + tid];
    __syncthreads();

    if (tid < 16) {
        const int j = tid;
        float m = -1e30f;
#pragma unroll
        for (int i = 0; i < 16; i++) m = fmaxf(m, sd[i * 16 + j]);
        float e[16];
        float s = 0.f;
#pragma unroll
        for (int i = 0; i < 16; i++) {
            e[i] = __expf(sd[i * 16 + j] - m);
            s += e[i];
        }
        float inv = 1.f / s;
#pragma unroll
        for (int i = 0; i < 16; i++) sw[i * 16 + j] = e[i] * inv;
    }
    __syncthreads();

    const int pix = chunk * 1024 + tid * 4;
    const float* vbase = g_value + ((size_t)b * En * Cn + c) * HWn + pix;
    F4U v[16];
#pragma unroll
    for (int i = 0; i < 16; i++)
        v[i].f = *(const float4*)(vbase + (size_t)i * Cn * HWn);

    float* obase = out + ((size_t)b * En * Cn + c) * HWn + pix;
    for (int j = 0; j < 16; j++) {
        unsigned long long a0 = 0ull, a1 = 0ull;
#pragma unroll
        for (int i = 0; i < 16; i++) {
            unsigned long long wp = pack2(sw[i * 16 + j]);
            a0 = fma2(wp, v[i].u[0], a0);
            a1 = fma2(wp, v[i].u[1], a1);
        }
        float f0, f1, f2, f3;
        unpack2(a0, f0, f1);
        unpack2(a1, f2, f3);
        float4 o = make_float4(selu_f(f0), selu_f(f1), selu_f(f2), selu_f(f3));
        *(float4*)(obase + (size_t)j * Cn * HWn) = o;
    }
}

// ---------------- launcher ----------------
extern "C" void kernel_launch(void* const* d_in, const int* in_sizes, int n_in,
                              void* d_out, int out_size) {
    const float* in = (const float*)d_in[0];
    const float* Wv = (const float*)d_in[1];
    const float* bv = (const float*)d_in[2];
    const float* Wk = (const float*)d_in[3];
    const float* bk = (const float*)d_in[4];
    const float* Wq = (const float*)d_in[5];
    const float* bq = (const float*)d_in[6];
    float* out = (float*)d_out;

    cudaFuncSetAttribute(conv_tc_kernel, cudaFuncAttributeMaxDynamicSharedMemorySize,
                         SM_A_TOTAL);
    cudaFuncSetAttribute(gram_kernel, cudaFuncAttributeMaxDynamicSharedMemorySize,
                         2 * 16 * 516 * (int)sizeof(float));

    prep_kernel<<<1, 192>>>(Wv, bv, Wk, bk, Wq, bq);
    conv_tc_kernel<<<dim3(HWn / 128, En, Bn), 512, SM_A_TOTAL>>>(in);
    gram_kernel<<<Bn * Cn, 256, 2 * 16 * 516 * sizeof(float)>>>();
    apply_kernel<<<dim3(4, Cn, Bn), 256>>>(out);
}

// round 13
// speedup vs baseline: 1.5387x; 1.2325x over previous
#include <cuda_runtime.h>
#include <cuda_bf16.h>
#include <cstdint>

// Problem constants
#define Bn   8
#define En   16
#define CINn 64
#define Cn   64
#define HWn  4096

// ---------------- scratch (device globals; no runtime allocation) ----------------
__device__ float g_value[(size_t)Bn * En * Cn * HWn];       // 134 MB
// K,Q packed bf16 (hi | lo<<16), layout [b][ck 0..127][e][px]; ck<64 = K, else Q
__device__ uint32_t g_KQ[(size_t)Bn * 128 * En * HWn];      // 268 MB
__device__ float g_dots[Bn * Cn * En * En];                 // 512 KB
__device__ __align__(16) __nv_bfloat16 g_Wh[192 * 64];      // stacked V,K,Q weights hi
__device__ __align__(16) __nv_bfloat16 g_Wl[192 * 64];      // lo
__device__ float g_biasA[192];

// ---------------- small helpers ----------------
__device__ __forceinline__ unsigned long long fma2(unsigned long long a,
                                                   unsigned long long b,
                                                   unsigned long long c) {
    unsigned long long d;
    asm("fma.rn.f32x2 %0, %1, %2, %3;" : "=l"(d) : "l"(a), "l"(b), "l"(c));
    return d;
}
__device__ __forceinline__ unsigned long long pack2(float x) {
    unsigned long long d;
    unsigned int u = __float_as_uint(x);
    asm("mov.b64 %0, {%1, %2};" : "=l"(d) : "r"(u), "r"(u));
    return d;
}
__device__ __forceinline__ void unpack2(unsigned long long v, float& lo, float& hi) {
    unsigned int a, b;
    asm("mov.b64 {%0, %1}, %2;" : "=r"(a), "=r"(b) : "l"(v));
    lo = __uint_as_float(a);
    hi = __uint_as_float(b);
}
union F2U {
    float2 f;
    unsigned long long u;
};
__device__ __forceinline__ float selu_f(float x) {
    const float sc = 1.0507009873554805f;
    const float sa = 1.7580993408473766f;  // sc * alpha
    return x > 0.f ? sc * x : sa * (__expf(x) - 1.f);
}
__device__ __forceinline__ uint32_t smem_u32(const void* p) {
    uint32_t a;
    asm("{ .reg .u64 t; cvta.to.shared.u64 t, %1; cvt.u32.u64 %0, t; }" : "=r"(a) : "l"(p));
    return a;
}
// pack fp32 -> (bf16 hi) | (bf16 lo << 16)
__device__ __forceinline__ uint32_t packhl(float v) {
    __nv_bfloat16 h = __float2bfloat16(v);
    __nv_bfloat16 l = __float2bfloat16(v - __bfloat162float(h));
    return (uint32_t)__bfloat16_as_ushort(h) |
           ((uint32_t)__bfloat16_as_ushort(l) << 16);
}

// ---------------- portable tensor-core primitives (sm_80+ PTX) ----------------
__device__ __forceinline__ void ldm_x4(uint32_t& a0, uint32_t& a1, uint32_t& a2,
                                       uint32_t& a3, uint32_t addr) {
    asm volatile("ldmatrix.sync.aligned.m8n8.x4.shared.b16 {%0,%1,%2,%3}, [%4];"
                 : "=r"(a0), "=r"(a1), "=r"(a2), "=r"(a3) : "r"(addr));
}
__device__ __forceinline__ void ldm_x2(uint32_t& b0, uint32_t& b1, uint32_t addr) {
    asm volatile("ldmatrix.sync.aligned.m8n8.x2.shared.b16 {%0,%1}, [%2];"
                 : "=r"(b0), "=r"(b1) : "r"(addr));
}
__device__ __forceinline__ void mma_bf16(float* d, uint32_t a0, uint32_t a1,
                                         uint32_t a2, uint32_t a3,
                                         uint32_t b0, uint32_t b1) {
    asm volatile(
        "mma.sync.aligned.m16n8k16.row.col.f32.bf16.bf16.f32 "
        "{%0,%1,%2,%3}, {%4,%5,%6,%7}, {%8,%9}, {%0,%1,%2,%3};"
        : "+f"(d[0]), "+f"(d[1]), "+f"(d[2]), "+f"(d[3])
        : "r"(a0), "r"(a1), "r"(a2), "r"(a3), "r"(b0), "r"(b1));
}

// ---------------- kernel 0: weight split to bf16 hi/lo + bias ----------------
__global__ void prep_kernel(const float* __restrict__ Wv, const float* __restrict__ bv,
                            const float* __restrict__ Wk, const float* __restrict__ bk,
                            const float* __restrict__ Wq, const float* __restrict__ bq) {
    int r = threadIdx.x;  // 0..191
    const float* Ws = (r < 64) ? Wv : (r < 128) ? Wk : Wq;
    const float* bs = (r < 64) ? bv : (r < 128) ? bk : bq;
    int rr = r & 63;
    for (int a = 0; a < 64; a++) {
        float w = Ws[rr * 64 + a];
        __nv_bfloat16 hi = __float2bfloat16(w);
        __nv_bfloat16 lo = __float2bfloat16(w - __bfloat162float(hi));
        g_Wh[r * 64 + a] = hi;
        g_Wl[r * 64 + a] = lo;
    }
    g_biasA[r] = bs[rr];
}

// ---------------- kernel A: warp-MMA 1x1 convs (V,K,Q) ----------------
// Per block: one (b,e), 128-pixel tile. GEMM M=128 px, N=192 outs, K=64.
// 3x-bf16 precision split (hi*hi + lo*hi + hi*lo), fp32 accumulators.
#define SM_AH   0
#define SM_AL   18432
#define SM_BH   36864
#define SM_BL   64512
#define SM_BIAS 92160
#define SM_A_TOTAL (92160 + 768)
#define ASTR 144           // bytes per A/B smem row (72 bf16)

__global__ __launch_bounds__(512, 1) void conv_tc_kernel(const float* __restrict__ in) {
    extern __shared__ char smem[];
    const uint32_t sb = smem_u32(smem);
    const int tid = threadIdx.x;
    const int w = tid >> 5;
    const int lane = tid & 31;
    const int px0 = blockIdx.x * 128;
    const int e = blockIdx.y;
    const int b = blockIdx.z;

    // ---- stage 1: coalesced X load -> fp32 bounce [64 a][132 px] ----
    {
        const float* xb = in + ((size_t)(b * En + e) * CINn) * HWn + px0;
        float* sT = (float*)(smem + SM_BH);
#pragma unroll
        for (int k = 0; k < 4; k++) {
            int idx = tid + k * 512;        // 0..2047
            int a = idx >> 5;
            int p4 = idx & 31;
            float4 v = *(const float4*)(xb + (size_t)a * HWn + p4 * 4);
            *(float4*)(sT + a * 132 + p4 * 4) = v;
        }
    }
    if (tid < 192) ((float*)(smem + SM_BIAS))[tid] = g_biasA[tid];
    __syncthreads();

    // ---- stage 2: transpose + bf16 hi/lo split -> A tiles [px][72] ----
    {
        const float* sT = (const float*)(smem + SM_BH);
        const int px = tid & 127;
        const int a0g = (tid >> 7) * 16;
#pragma unroll
        for (int q2 = 0; q2 < 2; q2++) {
            int a0 = a0g + q2 * 8;
            union { uint4 u; __nv_bfloat16 h[8]; } hi, lo;
#pragma unroll
            for (int q = 0; q < 8; q++) {
                float x = sT[(a0 + q) * 132 + px];
                __nv_bfloat16 h = __float2bfloat16(x);
                hi.h[q] = h;
                lo.h[q] = __float2bfloat16(x - __bfloat162float(h));
            }
            *(uint4*)(smem + SM_AH + px * ASTR + a0 * 2) = hi.u;
            *(uint4*)(smem + SM_AL + px * ASTR + a0 * 2) = lo.u;
        }
    }
    __syncthreads();   // bounce dead; load weights over it

    // ---- stage 3: weights -> smem [192 n][72 a] bf16 hi/lo ----
    {
        const uint4* wh = (const uint4*)g_Wh;
        const uint4* wl = (const uint4*)g_Wl;
#pragma unroll
        for (int k = 0; k < 3; k++) {
            int idx = tid + k * 512;        // 0..1535
            int row = idx >> 3;
            int c16 = idx & 7;
            uint32_t dst = row * ASTR + c16 * 16;
            *(uint4*)(smem + SM_BH + dst) = wh[idx];
            *(uint4*)(smem + SM_BL + dst) = wl[idx];
        }
    }
    __syncthreads();

    // ---- MMA: warp = 16 px strip x 96-output half ----
    const int m0 = (w & 7) * 16;
    const int nh = (w >> 3) * 96;

    float acc[12][4];
#pragma unroll
    for (int t = 0; t < 12; t++)
#pragma unroll
        for (int r = 0; r < 4; r++) acc[t][r] = 0.f;

    const uint32_t arow_base = (uint32_t)((m0 + (lane & 15)) * ASTR + (lane >> 4) * 16);
    const uint32_t brow_base = (uint32_t)((nh + (lane & 7)) * ASTR + ((lane >> 3) & 1) * 16);

#pragma unroll
    for (int pass = 0; pass < 3; pass++) {
        const uint32_t Abase = sb + ((pass == 1) ? SM_AL : SM_AH) + arow_base;
        const uint32_t Bbase = sb + ((pass == 2) ? SM_BL : SM_BH) + brow_base;
#pragma unroll
        for (int k = 0; k < 4; k++) {
            uint32_t a0, a1, a2, a3;
            ldm_x4(a0, a1, a2, a3, Abase + k * 32);
#pragma unroll
            for (int t = 0; t < 12; t++) {
                uint32_t b0, b1;
                ldm_x2(b0, b1, Bbase + k * 32 + t * (8 * ASTR));
                mma_bf16(acc[t], a0, a1, a2, a3, b0, b1);
            }
        }
    }

    // ---- epilogue: bias + V fp32 / K,Q SELU+bf16-hi/lo-packed ----
    {
        const float* sBias = (const float*)(smem + SM_BIAS);
        const int pxa = m0 + (lane >> 2);
        const size_t ebaseV = ((size_t)(b * En + e) * Cn) * HWn + px0;
#pragma unroll
        for (int t = 0; t < 12; t++) {
            const int n0 = nh + t * 8;
            const int c = n0 + (lane & 3) * 2;
            float v0 = acc[t][0] + sBias[c];
            float v1 = acc[t][1] + sBias[c + 1];
            float v2 = acc[t][2] + sBias[c];
            float v3 = acc[t][3] + sBias[c + 1];
            if (n0 < 64) {
                float* p0 = g_value + ebaseV + (size_t)c * HWn + pxa;
                float* p1 = g_value + ebaseV + (size_t)(c + 1) * HWn + pxa;
                p0[0] = v0;
                p1[0] = v1;
                p0[8] = v2;
                p1[8] = v3;
            } else {
                const int ck = c - 64;     // 0..127 (K then Q)
                uint32_t* p0 = g_KQ + ((size_t)(b * 128 + ck) * En + e) * HWn + px0 + pxa;
                uint32_t* p1 = g_KQ + ((size_t)(b * 128 + ck + 1) * En + e) * HWn + px0 + pxa;
                p0[0] = packhl(selu_f(v0));
                p1[0] = packhl(selu_f(v1));
                p0[8] = packhl(selu_f(v2));
                p1[8] = packhl(selu_f(v3));
            }
        }
    }
}

// ---------------- kernel B: gram via tensor cores ----------------
// Per block (b,c): dots[i,j] = sum_px K[i,px]*Q[j,px].  GEMM M=16, N=16, K=4096.
// bf16 hi/lo 3-pass split; 8 warps each own a 32-px sub-slice, reduce via smem.
// GPX=256 px per chunk; smem rows are GSTR=264 bf16 (256 px + 8 pad) -- the
// R12 bug was GPX=512 overflowing these rows.
#define GPX  256               // px per chunk
#define GSTR 264               // bf16 per smem row (528 B)
#define PLW  (16 * GSTR / 2)   // uint32 per plane = 2112

__global__ __launch_bounds__(256) void gram_kernel() {
    __shared__ __align__(16) uint32_t sp[4 * PLW];   // planes: Kh,Kl,Qh,Ql (33792 B)
    __shared__ float sred[8][256];
    const int tid = threadIdx.x;
    const int w = tid >> 5;
    const int lane = tid & 31;
    const int b = blockIdx.x >> 6;
    const int c = blockIdx.x & 63;
    const uint32_t sb = smem_u32(sp);

    const size_t kbase = ((size_t)(b * 128 + c) * En) * HWn;
    const size_t qbase = ((size_t)(b * 128 + 64 + c) * En) * HWn;

    float acc[2][4];
#pragma unroll
    for (int jt = 0; jt < 2; jt++)
#pragma unroll
        for (int r = 0; r < 4; r++) acc[jt][r] = 0.f;

    const uint32_t a_off = (uint32_t)((lane & 15) * (GSTR * 2) + (lane >> 4) * 16);
    const uint32_t b_off = (uint32_t)((lane & 7) * (GSTR * 2) + ((lane >> 3) & 1) * 16);
    const uint32_t kb0 = (uint32_t)(w * 64);      // warp's 32-px slice (bytes)

    for (int ch = 0; ch < HWn / GPX; ch++) {
        __syncthreads();
        // ---- stage + de-interleave hi/lo: 2048 uint4 loads (256 px x 16 e x {K,Q}) ----
#pragma unroll
        for (int z = 0; z < 8; z++) {
            int idx = tid + z * 256;          // 0..2047
            int t = idx >> 10;                // 0=K, 1=Q
            int rem = idx & 1023;
            int row = rem >> 6;               // e
            int q4 = rem & 63;                // uint4 index within 256-px row
            size_t src = (t ? qbase : kbase) + (size_t)row * HWn + ch * GPX + q4 * 4;
            uint4 v = *(const uint4*)(g_KQ + src);
            uint32_t h0 = (v.x & 0xFFFFu) | (v.y << 16);
            uint32_t h1 = (v.z & 0xFFFFu) | (v.w << 16);
            uint32_t l0 = (v.x >> 16) | (v.y & 0xFFFF0000u);
            uint32_t l1 = (v.z >> 16) | (v.w & 0xFFFF0000u);
            uint2* dh = (uint2*)(sp + (t * 2) * PLW) + row * (GSTR / 4) + q4;
            uint2* dl = (uint2*)(sp + (t * 2 + 1) * PLW) + row * (GSTR / 4) + q4;
            *dh = make_uint2(h0, h1);
            *dl = make_uint2(l0, l1);
        }
        __syncthreads();

        // ---- MMA on this warp's 32-px slice (2 k-steps of 16) ----
        const uint32_t kh = sb;
        const uint32_t kl = sb + 1 * (PLW * 4);
        const uint32_t qh = sb + 2 * (PLW * 4);
        const uint32_t ql = sb + 3 * (PLW * 4);
#pragma unroll
        for (int kk = 0; kk < 2; kk++) {
            const uint32_t off = kb0 + kk * 32;
            uint32_t ah0, ah1, ah2, ah3, al0, al1, al2, al3;
            ldm_x4(ah0, ah1, ah2, ah3, kh + a_off + off);
            ldm_x4(al0, al1, al2, al3, kl + a_off + off);
            uint32_t bh0, bh1, bh2, bh3, bl0, bl1, bl2, bl3;
            ldm_x2(bh0, bh1, qh + b_off + off);
            ldm_x2(bh2, bh3, qh + b_off + 8 * (GSTR * 2) + off);
            ldm_x2(bl0, bl1, ql + b_off + off);
            ldm_x2(bl2, bl3, ql + b_off + 8 * (GSTR * 2) + off);
            mma_bf16(acc[0], ah0, ah1, ah2, ah3, bh0, bh1);   // hi*hi
            mma_bf16(acc[1], ah0, ah1, ah2, ah3, bh2, bh3);
            mma_bf16(acc[0], al0, al1, al2, al3, bh0, bh1);   // lo*hi
            mma_bf16(acc[1], al0, al1, al2, al3, bh2, bh3);
            mma_bf16(acc[0], ah0, ah1, ah2, ah3, bl0, bl1);   // hi*lo
            mma_bf16(acc[1], ah0, ah1, ah2, ah3, bl2, bl3);
        }
    }

    // ---- cross-warp reduce ----
    {
        const int row = lane >> 2;
        const int c0 = (lane & 3) * 2;
#pragma unroll
        for (int jt = 0; jt < 2; jt++) {
            sred[w][row * 16 + jt * 8 + c0]           = acc[jt][0];
            sred[w][row * 16 + jt * 8 + c0 + 1]       = acc[jt][1];
            sred[w][(row + 8) * 16 + jt * 8 + c0]     = acc[jt][2];
            sred[w][(row + 8) * 16 + jt * 8 + c0 + 1] = acc[jt][3];
        }
    }
    __syncthreads();
    float s = 0.f;
#pragma unroll
    for (int ww = 0; ww < 8; ww++) s += sred[ww][tid];
    g_dots[blockIdx.x * 256 + tid] = s;
}

// ---------------- kernel C: softmax + weighted mix + SELU ----------------
// mean-centering cancels: out[b,j,c,hw] = selu( sum_i softmax_i(dots)[i,j] * V[b,i,c,hw] )
__global__ __launch_bounds__(256) void apply_kernel(float* __restrict__ out) {
    __shared__ float sd[256];
    __shared__ float sw[256];
    const int tid = threadIdx.x;
    const int chunk = blockIdx.x;   // 0..7  (512 pixels each)
    const int c = blockIdx.y;
    const int b = blockIdx.z;

    sd[tid] = g_dots[b * (Cn * En * En) + c * (En * En) + tid];
    __syncthreads();

    if (tid < 16) {
        const int j = tid;
        float m = -1e30f;
#pragma unroll
        for (int i = 0; i < 16; i++) m = fmaxf(m, sd[i * 16 + j]);
        float e[16];
        float s = 0.f;
#pragma unroll
        for (int i = 0; i < 16; i++) {
            e[i] = __expf(sd[i * 16 + j] - m);
            s += e[i];
        }
        float inv = 1.f / s;
#pragma unroll
        for (int i = 0; i < 16; i++) sw[i * 16 + j] = e[i] * inv;
    }
    __syncthreads();

    const int pix = chunk * 512 + tid * 2;
    const float* vbase = g_value + ((size_t)b * En * Cn + c) * HWn + pix;
    F2U v[16];
#pragma unroll
    for (int i = 0; i < 16; i++)
        v[i].f = *(const float2*)(vbase + (size_t)i * Cn * HWn);

    float* obase = out + ((size_t)b * En * Cn + c) * HWn + pix;
    for (int j = 0; j < 16; j++) {
        unsigned long long a0 = 0ull;
#pragma unroll
        for (int i = 0; i < 16; i++)
            a0 = fma2(pack2(sw[i * 16 + j]), v[i].u, a0);
        float f0, f1;
        unpack2(a0, f0, f1);
        F2U o;
        o.f = make_float2(selu_f(f0), selu_f(f1));
        *(float2*)(obase + (size_t)j * Cn * HWn) = o.f;
    }
}

// ---------------- launcher ----------------
extern "C" void kernel_launch(void* const* d_in, const int* in_sizes, int n_in,
                              void* d_out, int out_size) {
    const float* in = (const float*)d_in[0];
    const float* Wv = (const float*)d_in[1];
    const float* bv = (const float*)d_in[2];
    const float* Wk = (const float*)d_in[3];
    const float* bk = (const float*)d_in[4];
    const float* Wq = (const float*)d_in[5];
    const float* bq = (const float*)d_in[6];
    float* out = (float*)d_out;

    cudaFuncSetAttribute(conv_tc_kernel, cudaFuncAttributeMaxDynamicSharedMemorySize,
                         SM_A_TOTAL);

    prep_kernel<<<1, 192>>>(Wv, bv, Wk, bk, Wq, bq);
    conv_tc_kernel<<<dim3(HWn / 128, En, Bn), 512, SM_A_TOTAL>>>(in);
    gram_kernel<<<Bn * Cn, 256>>>();
    apply_kernel<<<dim3(8, Cn, Bn), 256>>>(out);
}

// round 14
// speedup vs baseline: 1.6755x; 1.0889x over previous
#include <cuda_runtime.h>
#include <cuda_bf16.h>
#include <cstdint>

// Problem constants
#define Bn   8
#define En   16
#define CINn 64
#define Cn   64
#define HWn  4096

// ---------------- scratch (device globals; no runtime allocation) ----------------
__device__ float g_value[(size_t)Bn * En * Cn * HWn];       // 134 MB
// K,Q packed bf16 (hi | lo<<16), layout [b][ck 0..127][e][px]; ck<64 = K, else Q
__device__ uint32_t g_KQ[(size_t)Bn * 128 * En * HWn];      // 268 MB
__device__ float g_dots[Bn * Cn * En * En];                 // 512 KB
__device__ __align__(16) __nv_bfloat16 g_Wh[192 * 64];      // stacked V,K,Q weights hi
__device__ __align__(16) __nv_bfloat16 g_Wl[192 * 64];      // lo
__device__ float g_biasA[192];

// ---------------- small helpers ----------------
__device__ __forceinline__ unsigned long long fma2(unsigned long long a,
                                                   unsigned long long b,
                                                   unsigned long long c) {
    unsigned long long d;
    asm("fma.rn.f32x2 %0, %1, %2, %3;" : "=l"(d) : "l"(a), "l"(b), "l"(c));
    return d;
}
__device__ __forceinline__ unsigned long long pack2(float x) {
    unsigned long long d;
    unsigned int u = __float_as_uint(x);
    asm("mov.b64 %0, {%1, %2};" : "=l"(d) : "r"(u), "r"(u));
    return d;
}
__device__ __forceinline__ void unpack2(unsigned long long v, float& lo, float& hi) {
    unsigned int a, b;
    asm("mov.b64 {%0, %1}, %2;" : "=r"(a), "=r"(b) : "l"(v));
    lo = __uint_as_float(a);
    hi = __uint_as_float(b);
}
union F2U {
    float2 f;
    unsigned long long u;
};
__device__ __forceinline__ float selu_f(float x) {
    const float sc = 1.0507009873554805f;
    const float sa = 1.7580993408473766f;  // sc * alpha
    return x > 0.f ? sc * x : sa * (__expf(x) - 1.f);
}
__device__ __forceinline__ uint32_t smem_u32(const void* p) {
    uint32_t a;
    asm("{ .reg .u64 t; cvta.to.shared.u64 t, %1; cvt.u32.u64 %0, t; }" : "=r"(a) : "l"(p));
    return a;
}
// pack fp32 -> (bf16 hi) | (bf16 lo << 16)
__device__ __forceinline__ uint32_t packhl(float v) {
    __nv_bfloat16 h = __float2bfloat16(v);
    __nv_bfloat16 l = __float2bfloat16(v - __bfloat162float(h));
    return (uint32_t)__bfloat16_as_ushort(h) |
           ((uint32_t)__bfloat16_as_ushort(l) << 16);
}

// ---------------- portable tensor-core primitives (sm_80+ PTX) ----------------
__device__ __forceinline__ void ldm_x4(uint32_t& a0, uint32_t& a1, uint32_t& a2,
                                       uint32_t& a3, uint32_t addr) {
    asm volatile("ldmatrix.sync.aligned.m8n8.x4.shared.b16 {%0,%1,%2,%3}, [%4];"
                 : "=r"(a0), "=r"(a1), "=r"(a2), "=r"(a3) : "r"(addr));
}
__device__ __forceinline__ void ldm_x4t(uint32_t& a0, uint32_t& a1, uint32_t& a2,
                                        uint32_t& a3, uint32_t addr) {
    asm volatile("ldmatrix.sync.aligned.m8n8.x4.trans.shared.b16 {%0,%1,%2,%3}, [%4];"
                 : "=r"(a0), "=r"(a1), "=r"(a2), "=r"(a3) : "r"(addr));
}
__device__ __forceinline__ void ldm_x2(uint32_t& b0, uint32_t& b1, uint32_t addr) {
    asm volatile("ldmatrix.sync.aligned.m8n8.x2.shared.b16 {%0,%1}, [%2];"
                 : "=r"(b0), "=r"(b1) : "r"(addr));
}
__device__ __forceinline__ void mma_bf16(float* d, uint32_t a0, uint32_t a1,
                                         uint32_t a2, uint32_t a3,
                                         uint32_t b0, uint32_t b1) {
    asm volatile(
        "mma.sync.aligned.m16n8k16.row.col.f32.bf16.bf16.f32 "
        "{%0,%1,%2,%3}, {%4,%5,%6,%7}, {%8,%9}, {%0,%1,%2,%3};"
        : "+f"(d[0]), "+f"(d[1]), "+f"(d[2]), "+f"(d[3])
        : "r"(a0), "r"(a1), "r"(a2), "r"(a3), "r"(b0), "r"(b1));
}

// ---------------- kernel 0: weight split to bf16 hi/lo + bias ----------------
__global__ void prep_kernel(const float* __restrict__ Wv, const float* __restrict__ bv,
                            const float* __restrict__ Wk, const float* __restrict__ bk,
                            const float* __restrict__ Wq, const float* __restrict__ bq) {
    int r = threadIdx.x;  // 0..191
    const float* Ws = (r < 64) ? Wv : (r < 128) ? Wk : Wq;
    const float* bs = (r < 64) ? bv : (r < 128) ? bk : bq;
    int rr = r & 63;
    for (int a = 0; a < 64; a++) {
        float w = Ws[rr * 64 + a];
        __nv_bfloat16 hi = __float2bfloat16(w);
        __nv_bfloat16 lo = __float2bfloat16(w - __bfloat162float(hi));
        g_Wh[r * 64 + a] = hi;
        g_Wl[r * 64 + a] = lo;
    }
    g_biasA[r] = bs[rr];
}

// ---------------- kernel A: warp-MMA 1x1 convs, transpose-free orientation ------
// A = weights (M=192 outs, row-major [out][cin]) ; B = x (N=128 px, K=64 cin),
// stored k-major [a][px] in smem and fed to mma via ldmatrix.x4.trans.
// 3x-bf16 precision split: Wh*Xh + Wl*Xh + Wh*Xl, fp32 accumulators.
//
// smem byte layout:
//   B_hi  [64 a][136 px] bf16 (272 B rows)  @ 0       (17408)
//   B_lo                                    @ 17408   (17408)
//   A_hi  [192 out][72 a] bf16 (144 B rows) @ 34816   (27648)
//   A_lo                                    @ 62464   (27648)
//   bias  [192] f32                         @ 90112   (768)
#define SM_BH   0
#define SM_BL   17408
#define SM_AH   34816
#define SM_AL   62464
#define SM_BIAS 90112
#define SM_A_TOTAL (90112 + 768)
#define BSTR 272           // bytes per B smem row (136 bf16; 16B-aligned, 4 banks skew)
#define ASTR 144           // bytes per A smem row (72 bf16)

__global__ __launch_bounds__(768, 1) void conv_tc_kernel(const float* __restrict__ in) {
    extern __shared__ char smem[];
    const uint32_t sb = smem_u32(smem);
    const int tid = threadIdx.x;
    const int w = tid >> 5;
    const int lane = tid & 31;
    const int px0 = blockIdx.x * 128;
    const int e = blockIdx.y;
    const int b = blockIdx.z;

    // ---- stage 1: x load + bf16 hi/lo split, SAME layout (no transpose) ----
    {
        const float* xb = in + ((size_t)(b * En + e) * CINn) * HWn + px0;
#pragma unroll
        for (int k = 0; k < 3; k++) {
            int idx = tid + k * 768;          // 0..2047 (last iter partial)
            if (idx < 2048) {
                int a = idx >> 5;
                int p4 = idx & 31;
                float4 v = *(const float4*)(xb + (size_t)a * HWn + p4 * 4);
                __nv_bfloat16 h0 = __float2bfloat16(v.x);
                __nv_bfloat16 h1 = __float2bfloat16(v.y);
                __nv_bfloat16 h2 = __float2bfloat16(v.z);
                __nv_bfloat16 h3 = __float2bfloat16(v.w);
                uint2 hu, lu;
                hu.x = (uint32_t)__bfloat16_as_ushort(h0) |
                       ((uint32_t)__bfloat16_as_ushort(h1) << 16);
                hu.y = (uint32_t)__bfloat16_as_ushort(h2) |
                       ((uint32_t)__bfloat16_as_ushort(h3) << 16);
                __nv_bfloat16 l0 = __float2bfloat16(v.x - __bfloat162float(h0));
                __nv_bfloat16 l1 = __float2bfloat16(v.y - __bfloat162float(h1));
                __nv_bfloat16 l2 = __float2bfloat16(v.z - __bfloat162float(h2));
                __nv_bfloat16 l3 = __float2bfloat16(v.w - __bfloat162float(h3));
                lu.x = (uint32_t)__bfloat16_as_ushort(l0) |
                       ((uint32_t)__bfloat16_as_ushort(l1) << 16);
                lu.y = (uint32_t)__bfloat16_as_ushort(l2) |
                       ((uint32_t)__bfloat16_as_ushort(l3) << 16);
                *(uint2*)(smem + SM_BH + a * BSTR + p4 * 8) = hu;
                *(uint2*)(smem + SM_BL + a * BSTR + p4 * 8) = lu;
            }
        }
    }
    // ---- weights + bias (parallel with stage 1, different smem region) ----
    {
        const uint4* wh = (const uint4*)g_Wh;
        const uint4* wl = (const uint4*)g_Wl;
#pragma unroll
        for (int k = 0; k < 2; k++) {
            int idx = tid + k * 768;          // 0..1535 (16B chunks; 8 per 64-elem row)
            int row = idx >> 3;
            int c16 = idx & 7;
            uint32_t dst = row * ASTR + c16 * 16;
            *(uint4*)(smem + SM_AH + dst) = wh[idx];
            *(uint4*)(smem + SM_AL + dst) = wl[idx];
        }
        if (tid < 192) ((float*)(smem + SM_BIAS))[tid] = g_biasA[tid];
    }
    __syncthreads();

    // ---- MMA: warp = 16 outs x 64 px;  24 warps = 12 m-strips x 2 n-halves ----
    const int m0 = (w >> 1) * 16;
    const int n0 = (w & 1) * 64;

    float acc[8][4];
#pragma unroll
    for (int f = 0; f < 8; f++)
#pragma unroll
        for (int r = 0; r < 4; r++) acc[f][r] = 0.f;

    const uint32_t aAddr = sb + SM_AH +
        (uint32_t)((m0 + (lane & 15)) * ASTR + ((lane >> 4) & 1) * 16);
    const uint32_t krow = (lane & 7) + ((lane >> 3) & 1) * 8;   // 0..15
    const uint32_t bAddr = sb + SM_BH +
        krow * BSTR + (uint32_t)(n0 + ((lane >> 4) & 1) * 8) * 2;

#pragma unroll
    for (int pass = 0; pass < 3; pass++) {
        const uint32_t aP = aAddr + ((pass == 1) ? (uint32_t)(SM_AL - SM_AH) : 0u);
        const uint32_t bP = bAddr + ((pass == 2) ? (uint32_t)(SM_BL - SM_BH) : 0u);
#pragma unroll
        for (int kk = 0; kk < 4; kk++) {
            uint32_t a0, a1, a2, a3;
            ldm_x4(a0, a1, a2, a3, aP + kk * 32);
#pragma unroll
            for (int g = 0; g < 4; g++) {
                uint32_t b0, b1, b2, b3;
                ldm_x4t(b0, b1, b2, b3, bP + kk * (16 * BSTR) + g * 32);
                mma_bf16(acc[2 * g],     a0, a1, a2, a3, b0, b1);
                mma_bf16(acc[2 * g + 1], a0, a1, a2, a3, b2, b3);
            }
        }
    }

    // ---- epilogue: D rows = channels, cols = px;  float2 px-pair stores ----
    {
        const float* sBias = (const float*)(smem + SM_BIAS);
        const int ch0 = m0 + (lane >> 2);         // channel for d0,d1
        const int ch1 = ch0 + 8;                  // channel for d2,d3
        const int pe = (lane & 3) * 2;            // px pair offset within 8
        const float b0 = sBias[ch0];
        const float b1 = sBias[ch1];
        if (m0 < 64) {
            const size_t ebaseV = ((size_t)(b * En + e) * Cn) * HWn + px0 + n0 + pe;
            float* p0 = g_value + ebaseV + (size_t)ch0 * HWn;
            float* p1 = g_value + ebaseV + (size_t)ch1 * HWn;
#pragma unroll
            for (int f = 0; f < 8; f++) {
                *(float2*)(p0 + f * 8) = make_float2(acc[f][0] + b0, acc[f][1] + b0);
                *(float2*)(p1 + f * 8) = make_float2(acc[f][2] + b1, acc[f][3] + b1);
            }
        } else {
            const int ck0 = ch0 - 64;             // 0..127 (K then Q)
            const int ck1 = ch1 - 64;
            const size_t kqb = (size_t)(b * 128) * En * HWn + (size_t)e * HWn
                               + px0 + n0 + pe;
            uint32_t* q0 = g_KQ + kqb + (size_t)ck0 * (En * HWn);
            uint32_t* q1 = g_KQ + kqb + (size_t)ck1 * (En * HWn);
#pragma unroll
            for (int f = 0; f < 8; f++) {
                uint2 s0, s1;
                s0.x = packhl(selu_f(acc[f][0] + b0));
                s0.y = packhl(selu_f(acc[f][1] + b0));
                s1.x = packhl(selu_f(acc[f][2] + b1));
                s1.y = packhl(selu_f(acc[f][3] + b1));
                *(uint2*)(q0 + f * 8) = s0;
                *(uint2*)(q1 + f * 8) = s1;
            }
        }
    }
}

// ---------------- kernel B: gram via tensor cores (unchanged, passing) ----------
// Per block (b,c): dots[i,j] = sum_px K[i,px]*Q[j,px].  GEMM M=16, N=16, K=4096.
#define GPX  256               // px per chunk
#define GSTR 264               // bf16 per smem row (528 B)
#define PLW  (16 * GSTR / 2)   // uint32 per plane = 2112

__global__ __launch_bounds__(256) void gram_kernel() {
    __shared__ __align__(16) uint32_t sp[4 * PLW];   // planes: Kh,Kl,Qh,Ql (33792 B)
    __shared__ float sred[8][256];
    const int tid = threadIdx.x;
    const int w = tid >> 5;
    const int lane = tid & 31;
    const int b = blockIdx.x >> 6;
    const int c = blockIdx.x & 63;
    const uint32_t sb = smem_u32(sp);

    const size_t kbase = ((size_t)(b * 128 + c) * En) * HWn;
    const size_t qbase = ((size_t)(b * 128 + 64 + c) * En) * HWn;

    float acc[2][4];
#pragma unroll
    for (int jt = 0; jt < 2; jt++)
#pragma unroll
        for (int r = 0; r < 4; r++) acc[jt][r] = 0.f;

    const uint32_t a_off = (uint32_t)((lane & 15) * (GSTR * 2) + (lane >> 4) * 16);
    const uint32_t b_off = (uint32_t)((lane & 7) * (GSTR * 2) + ((lane >> 3) & 1) * 16);
    const uint32_t kb0 = (uint32_t)(w * 64);      // warp's 32-px slice (bytes)

    for (int ch = 0; ch < HWn / GPX; ch++) {
        __syncthreads();
#pragma unroll
        for (int z = 0; z < 8; z++) {
            int idx = tid + z * 256;          // 0..2047
            int t = idx >> 10;                // 0=K, 1=Q
            int rem = idx & 1023;
            int row = rem >> 6;               // e
            int q4 = rem & 63;                // uint4 index within 256-px row
            size_t src = (t ? qbase : kbase) + (size_t)row * HWn + ch * GPX + q4 * 4;
            uint4 v = *(const uint4*)(g_KQ + src);
            uint32_t h0 = (v.x & 0xFFFFu) | (v.y << 16);
            uint32_t h1 = (v.z & 0xFFFFu) | (v.w << 16);
            uint32_t l0 = (v.x >> 16) | (v.y & 0xFFFF0000u);
            uint32_t l1 = (v.z >> 16) | (v.w & 0xFFFF0000u);
            uint2* dh = (uint2*)(sp + (t * 2) * PLW) + row * (GSTR / 4) + q4;
            uint2* dl = (uint2*)(sp + (t * 2 + 1) * PLW) + row * (GSTR / 4) + q4;
            *dh = make_uint2(h0, h1);
            *dl = make_uint2(l0, l1);
        }
        __syncthreads();

        const uint32_t kh = sb;
        const uint32_t kl = sb + 1 * (PLW * 4);
        const uint32_t qh = sb + 2 * (PLW * 4);
        const uint32_t ql = sb + 3 * (PLW * 4);
#pragma unroll
        for (int kk = 0; kk < 2; kk++) {
            const uint32_t off = kb0 + kk * 32;
            uint32_t ah0, ah1, ah2, ah3, al0, al1, al2, al3;
            ldm_x4(ah0, ah1, ah2, ah3, kh + a_off + off);
            ldm_x4(al0, al1, al2, al3, kl + a_off + off);
            uint32_t bh0, bh1, bh2, bh3, bl0, bl1, bl2, bl3;
            ldm_x2(bh0, bh1, qh + b_off + off);
            ldm_x2(bh2, bh3, qh + b_off + 8 * (GSTR * 2) + off);
            ldm_x2(bl0, bl1, ql + b_off + off);
            ldm_x2(bl2, bl3, ql + b_off + 8 * (GSTR * 2) + off);
            mma_bf16(acc[0], ah0, ah1, ah2, ah3, bh0, bh1);   // hi*hi
            mma_bf16(acc[1], ah0, ah1, ah2, ah3, bh2, bh3);
            mma_bf16(acc[0], al0, al1, al2, al3, bh0, bh1);   // lo*hi
            mma_bf16(acc[1], al0, al1, al2, al3, bh2, bh3);
            mma_bf16(acc[0], ah0, ah1, ah2, ah3, bl0, bl1);   // hi*lo
            mma_bf16(acc[1], ah0, ah1, ah2, ah3, bl2, bl3);
        }
    }

    {
        const int row = lane >> 2;
        const int c0 = (lane & 3) * 2;
#pragma unroll
        for (int jt = 0; jt < 2; jt++) {
            sred[w][row * 16 + jt * 8 + c0]           = acc[jt][0];
            sred[w][row * 16 + jt * 8 + c0 + 1]       = acc[jt][1];
            sred[w][(row + 8) * 16 + jt * 8 + c0]     = acc[jt][2];
            sred[w][(row + 8) * 16 + jt * 8 + c0 + 1] = acc[jt][3];
        }
    }
    __syncthreads();
    float s = 0.f;
#pragma unroll
    for (int ww = 0; ww < 8; ww++) s += sred[ww][tid];
    g_dots[blockIdx.x * 256 + tid] = s;
}

// ---------------- kernel C: softmax + weighted mix + SELU (unchanged) -----------
__global__ __launch_bounds__(256) void apply_kernel(float* __restrict__ out) {
    __shared__ float sd[256];
    __shared__ float sw[256];
    const int tid = threadIdx.x;
    const int chunk = blockIdx.x;   // 0..7  (512 pixels each)
    const int c = blockIdx.y;
    const int b = blockIdx.z;

    sd[tid] = g_dots[b * (Cn * En * En) + c * (En * En) + tid];
    __syncthreads();

    if (tid < 16) {
        const int j = tid;
        float m = -1e30f;
#pragma unroll
        for (int i = 0; i < 16; i++) m = fmaxf(m, sd[i * 16 + j]);
        float e[16];
        float s = 0.f;
#pragma unroll
        for (int i = 0; i < 16; i++) {
            e[i] = __expf(sd[i * 16 + j] - m);
            s += e[i];
        }
        float inv = 1.f / s;
#pragma unroll
        for (int i = 0; i < 16; i++) sw[i * 16 + j] = e[i] * inv;
    }
    __syncthreads();

    const int pix = chunk * 512 + tid * 2;
    const float* vbase = g_value + ((size_t)b * En * Cn + c) * HWn + pix;
    F2U v[16];
#pragma unroll
    for (int i = 0; i < 16; i++)
        v[i].f = *(const float2*)(vbase + (size_t)i * Cn * HWn);

    float* obase = out + ((size_t)b * En * Cn + c) * HWn + pix;
    for (int j = 0; j < 16; j++) {
        unsigned long long a0 = 0ull;
#pragma unroll
        for (int i = 0; i < 16; i++)
            a0 = fma2(pack2(sw[i * 16 + j]), v[i].u, a0);
        float f0, f1;
        unpack2(a0, f0, f1);
        F2U o;
        o.f = make_float2(selu_f(f0), selu_f(f1));
        *(float2*)(obase + (size_t)j * Cn * HWn) = o.f;
    }
}

// ---------------- launcher ----------------
extern "C" void kernel_launch(void* const* d_in, const int* in_sizes, int n_in,
                              void* d_out, int out_size) {
    const float* in = (const float*)d_in[0];
    const float* Wv = (const float*)d_in[1];
    const float* bv = (const float*)d_in[2];
    const float* Wk = (const float*)d_in[3];
    const float* bk = (const float*)d_in[4];
    const float* Wq = (const float*)d_in[5];
    const float* bq = (const float*)d_in[6];
    float* out = (float*)d_out;

    cudaFuncSetAttribute(conv_tc_kernel, cudaFuncAttributeMaxDynamicSharedMemorySize,
                         SM_A_TOTAL);

    prep_kernel<<<1, 192>>>(Wv, bv, Wk, bk, Wq, bq);
    conv_tc_kernel<<<dim3(HWn / 128, En, Bn), 768, SM_A_TOTAL>>>(in);
    gram_kernel<<<Bn * Cn, 256>>>();
    apply_kernel<<<dim3(8, Cn, Bn), 256>>>(out);
}

// round 16
// speedup vs baseline: 1.7555x; 1.0478x over previous
#include <cuda_runtime.h>
#include <cuda_bf16.h>
#include <cstdint>

// Problem constants
#define Bn   8
#define En   16
#define CINn 64
#define Cn   64
#define HWn  4096

// ---------------- scratch (device globals; no runtime allocation) ----------------
__device__ float g_value[(size_t)Bn * En * Cn * HWn];       // 134 MB
// K,Q packed bf16 (hi | lo<<16), layout [b][ck 0..127][e][px]; ck<64 = K, else Q
__device__ uint32_t g_KQ[(size_t)Bn * 128 * En * HWn];      // 268 MB
__device__ float g_dots[Bn * Cn * En * En];                 // 512 KB
__device__ __align__(16) __nv_bfloat16 g_Wh[192 * 64];      // stacked V,K,Q weights hi
__device__ __align__(16) __nv_bfloat16 g_Wl[192 * 64];      // lo
__device__ float g_biasA[192];

// ---------------- small helpers ----------------
__device__ __forceinline__ unsigned long long fma2(unsigned long long a,
                                                   unsigned long long b,
                                                   unsigned long long c) {
    unsigned long long d;
    asm("fma.rn.f32x2 %0, %1, %2, %3;" : "=l"(d) : "l"(a), "l"(b), "l"(c));
    return d;
}
__device__ __forceinline__ unsigned long long pack2(float x) {
    unsigned long long d;
    unsigned int u = __float_as_uint(x);
    asm("mov.b64 %0, {%1, %2};" : "=l"(d) : "r"(u), "r"(u));
    return d;
}
__device__ __forceinline__ void unpack2(unsigned long long v, float& lo, float& hi) {
    unsigned int a, b;
    asm("mov.b64 {%0, %1}, %2;" : "=r"(a), "=r"(b) : "l"(v));
    lo = __uint_as_float(a);
    hi = __uint_as_float(b);
}
union F2U {
    float2 f;
    unsigned long long u;
};
__device__ __forceinline__ float selu_f(float x) {
    const float sc = 1.0507009873554805f;
    const float sa = 1.7580993408473766f;  // sc * alpha
    return x > 0.f ? sc * x : sa * (__expf(x) - 1.f);
}
__device__ __forceinline__ uint32_t smem_u32(const void* p) {
    uint32_t a;
    asm("{ .reg .u64 t; cvta.to.shared.u64 t, %1; cvt.u32.u64 %0, t; }" : "=r"(a) : "l"(p));
    return a;
}
// pack fp32 -> (bf16 hi) | (bf16 lo << 16)
__device__ __forceinline__ uint32_t packhl(float v) {
    __nv_bfloat16 h = __float2bfloat16(v);
    __nv_bfloat16 l = __float2bfloat16(v - __bfloat162float(h));
    return (uint32_t)__bfloat16_as_ushort(h) |
           ((uint32_t)__bfloat16_as_ushort(l) << 16);
}

// ---------------- portable tensor-core primitives (sm_80+ PTX) ----------------
__device__ __forceinline__ void ldm_x4(uint32_t& a0, uint32_t& a1, uint32_t& a2,
                                       uint32_t& a3, uint32_t addr) {
    asm volatile("ldmatrix.sync.aligned.m8n8.x4.shared.b16 {%0,%1,%2,%3}, [%4];"
                 : "=r"(a0), "=r"(a1), "=r"(a2), "=r"(a3) : "r"(addr));
}
__device__ __forceinline__ void ldm_x4t(uint32_t& a0, uint32_t& a1, uint32_t& a2,
                                        uint32_t& a3, uint32_t addr) {
    asm volatile("ldmatrix.sync.aligned.m8n8.x4.trans.shared.b16 {%0,%1,%2,%3}, [%4];"
                 : "=r"(a0), "=r"(a1), "=r"(a2), "=r"(a3) : "r"(addr));
}
__device__ __forceinline__ void ldm_x2(uint32_t& b0, uint32_t& b1, uint32_t addr) {
    asm volatile("ldmatrix.sync.aligned.m8n8.x2.shared.b16 {%0,%1}, [%2];"
                 : "=r"(b0), "=r"(b1) : "r"(addr));
}
__device__ __forceinline__ void mma_bf16(float* d, uint32_t a0, uint32_t a1,
                                         uint32_t a2, uint32_t a3,
                                         uint32_t b0, uint32_t b1) {
    asm volatile(
        "mma.sync.aligned.m16n8k16.row.col.f32.bf16.bf16.f32 "
        "{%0,%1,%2,%3}, {%4,%5,%6,%7}, {%8,%9}, {%0,%1,%2,%3};"
        : "+f"(d[0]), "+f"(d[1]), "+f"(d[2]), "+f"(d[3])
        : "r"(a0), "r"(a1), "r"(a2), "r"(a3), "r"(b0), "r"(b1));
}

// ---------------- kernel 0: weight split to bf16 hi/lo + bias ----------------
__global__ void prep_kernel(const float* __restrict__ Wv, const float* __restrict__ bv,
                            const float* __restrict__ Wk, const float* __restrict__ bk,
                            const float* __restrict__ Wq, const float* __restrict__ bq) {
    int r = threadIdx.x;  // 0..191
    const float* Ws = (r < 64) ? Wv : (r < 128) ? Wk : Wq;
    const float* bs = (r < 64) ? bv : (r < 128) ? bk : bq;
    int rr = r & 63;
    for (int a = 0; a < 64; a++) {
        float w = Ws[rr * 64 + a];
        __nv_bfloat16 hi = __float2bfloat16(w);
        __nv_bfloat16 lo = __float2bfloat16(w - __bfloat162float(hi));
        g_Wh[r * 64 + a] = hi;
        g_Wl[r * 64 + a] = lo;
    }
    g_biasA[r] = bs[rr];
}

// ---------------- kernel A: pipelined warp-MMA 1x1 convs -----------------------
// A = weights (M=192 outs) ; B = x (N=128 px, K=64 cin) via ldmatrix.x4.trans.
// 3x-bf16 precision split: Wh*Xh + Wl*Xh + Wh*Xl, fp32 accumulators.
// Each block runs CTILES=4 consecutive 128-px tiles with double-buffered X
// planes: stage tile t+1 (LDG+split+STS) BEFORE the MMA of tile t, so the MMA
// latency hides the global loads. One __syncthreads per tile.
//
// smem byte layout:
//   B buf0: hi @ 0,      lo @ 17408     (34816 per buf; 272 B rows)
//   B buf1: hi @ 34816,  lo @ 52224
//   A_hi  [192 out][72 a] (144 B rows)  @ 69632  (27648)
//   A_lo                                @ 97280  (27648)
//   bias  [192] f32                     @ 124928 (768)
#define CTILES  4
#define BBUF_SZ 34816
#define BLO_OFF 17408
#define SM_AH   69632
#define SM_AL   97280
#define SM_BIAS 124928
#define SM_A_TOTAL (124928 + 768)
#define BSTR 272           // bytes per B smem row (136 bf16)
#define ASTR 144           // bytes per A smem row (72 bf16)

__device__ __forceinline__ void stage_x_tile(char* smem, uint32_t bufbase,
                                             const float* __restrict__ xb,
                                             int tid) {
#pragma unroll
    for (int k = 0; k < 3; k++) {
        int idx = tid + k * 768;          // 0..2047 (last iter partial)
        if (idx < 2048) {
            int a = idx >> 5;
            int p4 = idx & 31;
            float4 v = *(const float4*)(xb + (size_t)a * HWn + p4 * 4);
            __nv_bfloat16 h0 = __float2bfloat16(v.x);
            __nv_bfloat16 h1 = __float2bfloat16(v.y);
            __nv_bfloat16 h2 = __float2bfloat16(v.z);
            __nv_bfloat16 h3 = __float2bfloat16(v.w);
            uint2 hu, lu;
            hu.x = (uint32_t)__bfloat16_as_ushort(h0) |
                   ((uint32_t)__bfloat16_as_ushort(h1) << 16);
            hu.y = (uint32_t)__bfloat16_as_ushort(h2) |
                   ((uint32_t)__bfloat16_as_ushort(h3) << 16);
            __nv_bfloat16 l0 = __float2bfloat16(v.x - __bfloat162float(h0));
            __nv_bfloat16 l1 = __float2bfloat16(v.y - __bfloat162float(h1));
            __nv_bfloat16 l2 = __float2bfloat16(v.z - __bfloat162float(h2));
            __nv_bfloat16 l3 = __float2bfloat16(v.w - __bfloat162float(h3));
            lu.x = (uint32_t)__bfloat16_as_ushort(l0) |
                   ((uint32_t)__bfloat16_as_ushort(l1) << 16);
            lu.y = (uint32_t)__bfloat16_as_ushort(l2) |
                   ((uint32_t)__bfloat16_as_ushort(l3) << 16);
            *(uint2*)(smem + bufbase + a * BSTR + p4 * 8) = hu;
            *(uint2*)(smem + bufbase + BLO_OFF + a * BSTR + p4 * 8) = lu;
        }
    }
}

__global__ __launch_bounds__(768, 1) void conv_tc_kernel(const float* __restrict__ in) {
    extern __shared__ char smem[];
    const uint32_t sb = smem_u32(smem);
    const int tid = threadIdx.x;
    const int w = tid >> 5;
    const int lane = tid & 31;
    const int pxg = blockIdx.x * (CTILES * 128);
    const int e = blockIdx.y;
    const int b = blockIdx.z;
    const float* xbase = in + ((size_t)(b * En + e) * CINn) * HWn;

    // ---- weights + bias + tile-0 staging ----
    {
        const uint4* wh = (const uint4*)g_Wh;
        const uint4* wl = (const uint4*)g_Wl;
#pragma unroll
        for (int k = 0; k < 2; k++) {
            int idx = tid + k * 768;          // 0..1535 (16B chunks; 8 per 64-elem row)
            int row = idx >> 3;
            int c16 = idx & 7;
            uint32_t dst = row * ASTR + c16 * 16;
            *(uint4*)(smem + SM_AH + dst) = wh[idx];
            *(uint4*)(smem + SM_AL + dst) = wl[idx];
        }
        if (tid < 192) ((float*)(smem + SM_BIAS))[tid] = g_biasA[tid];
    }
    stage_x_tile(smem, 0, xbase + pxg, tid);
    __syncthreads();

    // ---- MMA thread mapping: warp = 16 outs x 64 px; 24 warps = 12 m x 2 n ----
    const int m0 = (w >> 1) * 16;
    const int n0 = (w & 1) * 64;
    const uint32_t aAddr = sb + SM_AH +
        (uint32_t)((m0 + (lane & 15)) * ASTR + ((lane >> 4) & 1) * 16);
    const uint32_t krow = (lane & 7) + ((lane >> 3) & 1) * 8;   // 0..15
    const uint32_t bOff =
        krow * BSTR + (uint32_t)(n0 + ((lane >> 4) & 1) * 8) * 2;

    // epilogue-constant pieces
    const float* sBias = (const float*)(smem + SM_BIAS);
    const int ch0 = m0 + (lane >> 2);
    const int ch1 = ch0 + 8;
    const int pe = (lane & 3) * 2;
    const float bia0 = g_biasA[ch0];
    const float bia1 = g_biasA[ch1];

    for (int t = 0; t < CTILES; t++) {
        // ---- stage NEXT tile into the alternate buffer (overlaps with MMA) ----
        if (t + 1 < CTILES)
            stage_x_tile(smem, (uint32_t)(((t + 1) & 1) * BBUF_SZ),
                         xbase + pxg + (t + 1) * 128, tid);

        // ---- MMA on current buffer ----
        float acc[8][4];
#pragma unroll
        for (int f = 0; f < 8; f++)
#pragma unroll
            for (int r = 0; r < 4; r++) acc[f][r] = 0.f;

        const uint32_t bBuf = sb + (uint32_t)((t & 1) * BBUF_SZ) + bOff;
#pragma unroll
        for (int pass = 0; pass < 3; pass++) {
            const uint32_t aP = aAddr + ((pass == 1) ? (uint32_t)(SM_AL - SM_AH) : 0u);
            const uint32_t bP = bBuf + ((pass == 2) ? (uint32_t)BLO_OFF : 0u);
#pragma unroll
            for (int kk = 0; kk < 4; kk++) {
                uint32_t a0, a1, a2, a3;
                ldm_x4(a0, a1, a2, a3, aP + kk * 32);
#pragma unroll
                for (int g = 0; g < 4; g++) {
                    uint32_t b0, b1, b2, b3;
                    ldm_x4t(b0, b1, b2, b3, bP + kk * (16 * BSTR) + g * 32);
                    mma_bf16(acc[2 * g],     a0, a1, a2, a3, b0, b1);
                    mma_bf16(acc[2 * g + 1], a0, a1, a2, a3, b2, b3);
                }
            }
        }

        // ---- epilogue for tile t ----
        {
            const int px0 = pxg + t * 128;
            if (m0 < 64) {
                const size_t ebaseV = ((size_t)(b * En + e) * Cn) * HWn + px0 + n0 + pe;
                float* p0 = g_value + ebaseV + (size_t)ch0 * HWn;
                float* p1 = g_value + ebaseV + (size_t)ch1 * HWn;
#pragma unroll
                for (int f = 0; f < 8; f++) {
                    *(float2*)(p0 + f * 8) =
                        make_float2(acc[f][0] + bia0, acc[f][1] + bia0);
                    *(float2*)(p1 + f * 8) =
                        make_float2(acc[f][2] + bia1, acc[f][3] + bia1);
                }
            } else {
                const int ck0 = ch0 - 64;             // 0..127 (K then Q)
                const int ck1 = ch1 - 64;
                const size_t kqb = (size_t)(b * 128) * En * HWn + (size_t)e * HWn
                                   + px0 + n0 + pe;
                uint32_t* q0 = g_KQ + kqb + (size_t)ck0 * (En * HWn);
                uint32_t* q1 = g_KQ + kqb + (size_t)ck1 * (En * HWn);
#pragma unroll
                for (int f = 0; f < 8; f++) {
                    uint2 s0, s1;
                    s0.x = packhl(selu_f(acc[f][0] + bia0));
                    s0.y = packhl(selu_f(acc[f][1] + bia0));
                    s1.x = packhl(selu_f(acc[f][2] + bia1));
                    s1.y = packhl(selu_f(acc[f][3] + bia1));
                    *(uint2*)(q0 + f * 8) = s0;
                    *(uint2*)(q1 + f * 8) = s1;
                }
            }
        }
        __syncthreads();   // staged t+1 complete AND buf t free before next iter
    }
    (void)sBias;
}

// ---------------- kernel B: gram via tensor cores (unchanged, passing) ----------
// Per block (b,c): dots[i,j] = sum_px K[i,px]*Q[j,px].  GEMM M=16, N=16, K=4096.
#define GPX  256               // px per chunk
#define GSTR 264               // bf16 per smem row (528 B)
#define PLW  (16 * GSTR / 2)   // uint32 per plane = 2112

__global__ __launch_bounds__(256) void gram_kernel() {
    __shared__ __align__(16) uint32_t sp[4 * PLW];   // planes: Kh,Kl,Qh,Ql (33792 B)
    __shared__ float sred[8][256];
    const int tid = threadIdx.x;
    const int w = tid >> 5;
    const int lane = tid & 31;
    const int b = blockIdx.x >> 6;
    const int c = blockIdx.x & 63;
    const uint32_t sb = smem_u32(sp);

    const size_t kbase = ((size_t)(b * 128 + c) * En) * HWn;
    const size_t qbase = ((size_t)(b * 128 + 64 + c) * En) * HWn;

    float acc[2][4];
#pragma unroll
    for (int jt = 0; jt < 2; jt++)
#pragma unroll
        for (int r = 0; r < 4; r++) acc[jt][r] = 0.f;

    const uint32_t a_off = (uint32_t)((lane & 15) * (GSTR * 2) + (lane >> 4) * 16);
    const uint32_t b_off = (uint32_t)((lane & 7) * (GSTR * 2) + ((lane >> 3) & 1) * 16);
    const uint32_t kb0 = (uint32_t)(w * 64);      // warp's 32-px slice (bytes)

    for (int ch = 0; ch < HWn / GPX; ch++) {
        __syncthreads();
#pragma unroll
        for (int z = 0; z < 8; z++) {
            int idx = tid + z * 256;          // 0..2047
            int t = idx >> 10;                // 0=K, 1=Q
            int rem = idx & 1023;
            int row = rem >> 6;               // e
            int q4 = rem & 63;                // uint4 index within 256-px row
            size_t src = (t ? qbase : kbase) + (size_t)row * HWn + ch * GPX + q4 * 4;
            uint4 v = *(const uint4*)(g_KQ + src);
            uint32_t h0 = (v.x & 0xFFFFu) | (v.y << 16);
            uint32_t h1 = (v.z & 0xFFFFu) | (v.w << 16);
            uint32_t l0 = (v.x >> 16) | (v.y & 0xFFFF0000u);
            uint32_t l1 = (v.z >> 16) | (v.w & 0xFFFF0000u);
            uint2* dh = (uint2*)(sp + (t * 2) * PLW) + row * (GSTR / 4) + q4;
            uint2* dl = (uint2*)(sp + (t * 2 + 1) * PLW) + row * (GSTR / 4) + q4;
            *dh = make_uint2(h0, h1);
            *dl = make_uint2(l0, l1);
        }
        __syncthreads();

        const uint32_t kh = sb;
        const uint32_t kl = sb + 1 * (PLW * 4);
        const uint32_t qh = sb + 2 * (PLW * 4);
        const uint32_t ql = sb + 3 * (PLW * 4);
#pragma unroll
        for (int kk = 0; kk < 2; kk++) {
            const uint32_t off = kb0 + kk * 32;
            uint32_t ah0, ah1, ah2, ah3, al0, al1, al2, al3;
            ldm_x4(ah0, ah1, ah2, ah3, kh + a_off + off);
            ldm_x4(al0, al1, al2, al3, kl + a_off + off);
            uint32_t bh0, bh1, bh2, bh3, bl0, bl1, bl2, bl3;
            ldm_x2(bh0, bh1, qh + b_off + off);
            ldm_x2(bh2, bh3, qh + b_off + 8 * (GSTR * 2) + off);
            ldm_x2(bl0, bl1, ql + b_off + off);
            ldm_x2(bl2, bl3, ql + b_off + 8 * (GSTR * 2) + off);
            mma_bf16(acc[0], ah0, ah1, ah2, ah3, bh0, bh1);   // hi*hi
            mma_bf16(acc[1], ah0, ah1, ah2, ah3, bh2, bh3);
            mma_bf16(acc[0], al0, al1, al2, al3, bh0, bh1);   // lo*hi
            mma_bf16(acc[1], al0, al1, al2, al3, bh2, bh3);
            mma_bf16(acc[0], ah0, ah1, ah2, ah3, bl0, bl1);   // hi*lo
            mma_bf16(acc[1], ah0, ah1, ah2, ah3, bl2, bl3);
        }
    }

    {
        const int row = lane >> 2;
        const int c0 = (lane & 3) * 2;
#pragma unroll
        for (int jt = 0; jt < 2; jt++) {
            sred[w][row * 16 + jt * 8 + c0]           = acc[jt][0];
            sred[w][row * 16 + jt * 8 + c0 + 1]       = acc[jt][1];
            sred[w][(row + 8) * 16 + jt * 8 + c0]     = acc[jt][2];
            sred[w][(row + 8) * 16 + jt * 8 + c0 + 1] = acc[jt][3];
        }
    }
    __syncthreads();
    float s = 0.f;
#pragma unroll
    for (int ww = 0; ww < 8; ww++) s += sred[ww][tid];
    g_dots[blockIdx.x * 256 + tid] = s;
}

// ---------------- kernel C: softmax + weighted mix + SELU (unchanged) -----------
__global__ __launch_bounds__(256) void apply_kernel(float* __restrict__ out) {
    __shared__ float sd[256];
    __shared__ float sw[256];
    const int tid = threadIdx.x;
    const int chunk = blockIdx.x;   // 0..7  (512 pixels each)
    const int c = blockIdx.y;
    const int b = blockIdx.z;

    sd[tid] = g_dots[b * (Cn * En * En) + c * (En * En) + tid];
    __syncthreads();

    if (tid < 16) {
        const int j = tid;
        float m = -1e30f;
#pragma unroll
        for (int i = 0; i < 16; i++) m = fmaxf(m, sd[i * 16 + j]);
        float e[16];
        float s = 0.f;
#pragma unroll
        for (int i = 0; i < 16; i++) {
            e[i] = __expf(sd[i * 16 + j] - m);
            s += e[i];
        }
        float inv = 1.f / s;
#pragma unroll
        for (int i = 0; i < 16; i++) sw[i * 16 + j] = e[i] * inv;
    }
    __syncthreads();

    const int pix = chunk * 512 + tid * 2;
    const float* vbase = g_value + ((size_t)b * En * Cn + c) * HWn + pix;
    F2U v[16];
#pragma unroll
    for (int i = 0; i < 16; i++)
        v[i].f = *(const float2*)(vbase + (size_t)i * Cn * HWn);

    float* obase = out + ((size_t)b * En * Cn + c) * HWn + pix;
    for (int j = 0; j < 16; j++) {
        unsigned long long a0 = 0ull;
#pragma unroll
        for (int i = 0; i < 16; i++)
            a0 = fma2(pack2(sw[i * 16 + j]), v[i].u, a0);
        float f0, f1;
        unpack2(a0, f0, f1);
        F2U o;
        o.f = make_float2(selu_f(f0), selu_f(f1));
        *(float2*)(obase + (size_t)j * Cn * HWn) = o.f;
    }
}

// ---------------- launcher ----------------
extern "C" void kernel_launch(void* const* d_in, const int* in_sizes, int n_in,
                              void* d_out, int out_size) {
    const float* in = (const float*)d_in[0];
    const float* Wv = (const float*)d_in[1];
    const float* bv = (const float*)d_in[2];
    const float* Wk = (const float*)d_in[3];
    const float* bk = (const float*)d_in[4];
    const float* Wq = (const float*)d_in[5];
    const float* bq = (const float*)d_in[6];
    float* out = (float*)d_out;

    cudaFuncSetAttribute(conv_tc_kernel, cudaFuncAttributeMaxDynamicSharedMemorySize,
                         SM_A_TOTAL);

    prep_kernel<<<1, 192>>>(Wv, bv, Wk, bk, Wq, bq);
    conv_tc_kernel<<<dim3(HWn / (CTILES * 128), En, Bn), 768, SM_A_TOTAL>>>(in);
    gram_kernel<<<Bn * Cn, 256>>>();
    apply_kernel<<<dim3(8, Cn, Bn), 256>>>(out);
}

// round 17
// speedup vs baseline: 1.8191x; 1.0362x over previous
#include <cuda_runtime.h>
#include <cuda_bf16.h>
#include <cstdint>

// Problem constants
#define Bn   8
#define En   16
#define CINn 64
#define Cn   64
#define HWn  4096

// ---------------- scratch (device globals; no runtime allocation) ----------------
__device__ float g_value[(size_t)Bn * En * Cn * HWn];       // 134 MB
// K,Q packed bf16 (hi | lo<<16), layout [b][ck 0..127][e][px]; ck<64 = K, else Q
__device__ uint32_t g_KQ[(size_t)Bn * 128 * En * HWn];      // 268 MB
__device__ float g_dots[Bn * Cn * En * En];                 // 512 KB
__device__ __align__(16) __nv_bfloat16 g_Wh[192 * 64];      // stacked V,K,Q weights hi
__device__ __align__(16) __nv_bfloat16 g_Wl[192 * 64];      // lo
__device__ float g_biasA[192];

// ---------------- small helpers ----------------
__device__ __forceinline__ unsigned long long fma2(unsigned long long a,
                                                   unsigned long long b,
                                                   unsigned long long c) {
    unsigned long long d;
    asm("fma.rn.f32x2 %0, %1, %2, %3;" : "=l"(d) : "l"(a), "l"(b), "l"(c));
    return d;
}
__device__ __forceinline__ unsigned long long pack2(float x) {
    unsigned long long d;
    unsigned int u = __float_as_uint(x);
    asm("mov.b64 %0, {%1, %2};" : "=l"(d) : "r"(u), "r"(u));
    return d;
}
__device__ __forceinline__ unsigned long long pack64u(uint32_t a, uint32_t b) {
    unsigned long long d;
    asm("mov.b64 %0, {%1, %2};" : "=l"(d) : "r"(a), "r"(b));
    return d;
}
__device__ __forceinline__ void unpack2(unsigned long long v, float& lo, float& hi) {
    unsigned int a, b;
    asm("mov.b64 {%0, %1}, %2;" : "=r"(a), "=r"(b) : "l"(v));
    lo = __uint_as_float(a);
    hi = __uint_as_float(b);
}
union F2U {
    float2 f;
    unsigned long long u;
};
__device__ __forceinline__ float selu_f(float x) {
    const float sc = 1.0507009873554805f;
    const float sa = 1.7580993408473766f;  // sc * alpha
    return x > 0.f ? sc * x : sa * (__expf(x) - 1.f);
}
__device__ __forceinline__ uint32_t smem_u32(const void* p) {
    uint32_t a;
    asm("{ .reg .u64 t; cvta.to.shared.u64 t, %1; cvt.u32.u64 %0, t; }" : "=r"(a) : "l"(p));
    return a;
}
// packed bf16 conversion: returns bf(lo) | bf(hi)<<16   (RN rounding, same as
// __float2bfloat16) — first asm source lands in the HIGH half per PTX spec.
__device__ __forceinline__ uint32_t cvt_bf16x2(float hi, float lo) {
    uint32_t r;
    asm("cvt.rn.bf16x2.f32 %0, %1, %2;" : "=r"(r) : "f"(hi), "f"(lo));
    return r;
}
__device__ __forceinline__ uint32_t prmt(uint32_t a, uint32_t b, uint32_t sel) {
    uint32_t d;
    asm("prmt.b32 %0, %1, %2, %3;" : "=r"(d) : "r"(a), "r"(b), "r"(sel));
    return d;
}
// split a packed f32 pair into (hi-plane bf16x2, lo-plane bf16x2)
__device__ __forceinline__ void split_pair(float x0, float x1,
                                           unsigned long long x01,
                                           unsigned long long neg1,
                                           uint32_t& hplane, uint32_t& lplane) {
    uint32_t h = cvt_bf16x2(x1, x0);              // bf(x0) | bf(x1)<<16
    uint32_t w0 = h << 16;                        // f32 bits of bf(x0)
    uint32_t w1 = h & 0xFFFF0000u;                // f32 bits of bf(x1)
    unsigned long long hw = pack64u(w0, w1);
    unsigned long long lo64 = fma2(hw, neg1, x01);  // x - hi  (packed)
    float l0, l1;
    unpack2(lo64, l0, l1);
    hplane = h;
    lplane = cvt_bf16x2(l1, l0);
}
// pack two fp32 values -> two (bf16hi | bf16lo<<16) words
__device__ __forceinline__ uint2 packhl2(float v0, float v1,
                                         unsigned long long neg1) {
    F2U p;
    p.f = make_float2(v0, v1);
    uint32_t h, l;
    split_pair(v0, v1, p.u, neg1, h, l);
    uint2 r;
    r.x = prmt(h, l, 0x5410);   // {h.b0,h.b1,l.b0,l.b1}
    r.y = prmt(h, l, 0x7632);   // {h.b2,h.b3,l.b2,l.b3}
    return r;
}

// ---------------- portable tensor-core primitives (sm_80+ PTX) ----------------
__device__ __forceinline__ void ldm_x4(uint32_t& a0, uint32_t& a1, uint32_t& a2,
                                       uint32_t& a3, uint32_t addr) {
    asm volatile("ldmatrix.sync.aligned.m8n8.x4.shared.b16 {%0,%1,%2,%3}, [%4];"
                 : "=r"(a0), "=r"(a1), "=r"(a2), "=r"(a3) : "r"(addr));
}
__device__ __forceinline__ void ldm_x4t(uint32_t& a0, uint32_t& a1, uint32_t& a2,
                                        uint32_t& a3, uint32_t addr) {
    asm volatile("ldmatrix.sync.aligned.m8n8.x4.trans.shared.b16 {%0,%1,%2,%3}, [%4];"
                 : "=r"(a0), "=r"(a1), "=r"(a2), "=r"(a3) : "r"(addr));
}
__device__ __forceinline__ void ldm_x2(uint32_t& b0, uint32_t& b1, uint32_t addr) {
    asm volatile("ldmatrix.sync.aligned.m8n8.x2.shared.b16 {%0,%1}, [%2];"
                 : "=r"(b0), "=r"(b1) : "r"(addr));
}
__device__ __forceinline__ void mma_bf16(float* d, uint32_t a0, uint32_t a1,
                                         uint32_t a2, uint32_t a3,
                                         uint32_t b0, uint32_t b1) {
    asm volatile(
        "mma.sync.aligned.m16n8k16.row.col.f32.bf16.bf16.f32 "
        "{%0,%1,%2,%3}, {%4,%5,%6,%7}, {%8,%9}, {%0,%1,%2,%3};"
        : "+f"(d[0]), "+f"(d[1]), "+f"(d[2]), "+f"(d[3])
        : "r"(a0), "r"(a1), "r"(a2), "r"(a3), "r"(b0), "r"(b1));
}

// ---------------- kernel 0: weight split to bf16 hi/lo + bias ----------------
__global__ void prep_kernel(const float* __restrict__ Wv, const float* __restrict__ bv,
                            const float* __restrict__ Wk, const float* __restrict__ bk,
                            const float* __restrict__ Wq, const float* __restrict__ bq) {
    int r = threadIdx.x;  // 0..191
    const float* Ws = (r < 64) ? Wv : (r < 128) ? Wk : Wq;
    const float* bs = (r < 64) ? bv : (r < 128) ? bk : bq;
    int rr = r & 63;
    for (int a = 0; a < 64; a++) {
        float w = Ws[rr * 64 + a];
        __nv_bfloat16 hi = __float2bfloat16(w);
        __nv_bfloat16 lo = __float2bfloat16(w - __bfloat162float(hi));
        g_Wh[r * 64 + a] = hi;
        g_Wl[r * 64 + a] = lo;
    }
    g_biasA[r] = bs[rr];
}

// ---------------- kernel A: pipelined warp-MMA 1x1 convs -----------------------
// A = weights (M=192 outs) ; B = x (N=128 px, K=64 cin) via ldmatrix.x4.trans.
// 3x-bf16 precision split: Wh*Xh + Wl*Xh + Wh*Xl, fp32 accumulators.
// CTILES=4 tiles per block, double-buffered X staging overlapped with MMA.
//
// smem byte layout:
//   B buf0: hi @ 0,      lo @ 17408     (34816 per buf; 272 B rows)
//   B buf1: hi @ 34816,  lo @ 52224
//   A_hi  [192 out][72 a] (144 B rows)  @ 69632  (27648)
//   A_lo                                @ 97280  (27648)
//   bias  [192] f32                     @ 124928 (768)
#define CTILES  4
#define BBUF_SZ 34816
#define BLO_OFF 17408
#define SM_AH   69632
#define SM_AL   97280
#define SM_BIAS 124928
#define SM_A_TOTAL (124928 + 768)
#define BSTR 272           // bytes per B smem row (136 bf16)
#define ASTR 144           // bytes per A smem row (72 bf16)

__device__ __forceinline__ void stage_x_tile(char* smem, uint32_t bufbase,
                                             const float* __restrict__ xb,
                                             int tid, unsigned long long neg1) {
#pragma unroll
    for (int k = 0; k < 3; k++) {
        int idx = tid + k * 768;          // 0..2047 (last iter partial)
        if (idx < 2048) {
            int a = idx >> 5;
            int p4 = idx & 31;
            const float4* src = (const float4*)(xb + (size_t)a * HWn + p4 * 4);
            F2U p01, p23;
            {
                float4 v = *src;
                p01.f = make_float2(v.x, v.y);
                p23.f = make_float2(v.z, v.w);
            }
            uint2 hu, lu;
            split_pair(p01.f.x, p01.f.y, p01.u, neg1, hu.x, lu.x);
            split_pair(p23.f.x, p23.f.y, p23.u, neg1, hu.y, lu.y);
            *(uint2*)(smem + bufbase + a * BSTR + p4 * 8) = hu;
            *(uint2*)(smem + bufbase + BLO_OFF + a * BSTR + p4 * 8) = lu;
        }
    }
}

__global__ __launch_bounds__(768, 1) void conv_tc_kernel(const float* __restrict__ in) {
    extern __shared__ char smem[];
    const uint32_t sb = smem_u32(smem);
    const int tid = threadIdx.x;
    const int w = tid >> 5;
    const int lane = tid & 31;
    const int pxg = blockIdx.x * (CTILES * 128);
    const int e = blockIdx.y;
    const int b = blockIdx.z;
    const float* xbase = in + ((size_t)(b * En + e) * CINn) * HWn;
    const unsigned long long neg1 = pack2(-1.0f);

    // ---- weights + bias + tile-0 staging ----
    {
        const uint4* wh = (const uint4*)g_Wh;
        const uint4* wl = (const uint4*)g_Wl;
#pragma unroll
        for (int k = 0; k < 2; k++) {
            int idx = tid + k * 768;          // 0..1535 (16B chunks; 8 per 64-elem row)
            int row = idx >> 3;
            int c16 = idx & 7;
            uint32_t dst = row * ASTR + c16 * 16;
            *(uint4*)(smem + SM_AH + dst) = wh[idx];
            *(uint4*)(smem + SM_AL + dst) = wl[idx];
        }
        if (tid < 192) ((float*)(smem + SM_BIAS))[tid] = g_biasA[tid];
    }
    stage_x_tile(smem, 0, xbase + pxg, tid, neg1);
    __syncthreads();

    // ---- MMA thread mapping: warp = 16 outs x 64 px; 24 warps = 12 m x 2 n ----
    const int m0 = (w >> 1) * 16;
    const int n0 = (w & 1) * 64;
    const uint32_t aAddr = sb + SM_AH +
        (uint32_t)((m0 + (lane & 15)) * ASTR + ((lane >> 4) & 1) * 16);
    const uint32_t krow = (lane & 7) + ((lane >> 3) & 1) * 8;   // 0..15
    const uint32_t bOff =
        krow * BSTR + (uint32_t)(n0 + ((lane >> 4) & 1) * 8) * 2;

    // epilogue-constant pieces
    const int ch0 = m0 + (lane >> 2);
    const int ch1 = ch0 + 8;
    const int pe = (lane & 3) * 2;
    const float bia0 = g_biasA[ch0];
    const float bia1 = g_biasA[ch1];

    for (int t = 0; t < CTILES; t++) {
        // ---- stage NEXT tile into the alternate buffer (overlaps with MMA) ----
        if (t + 1 < CTILES)
            stage_x_tile(smem, (uint32_t)(((t + 1) & 1) * BBUF_SZ),
                         xbase + pxg + (t + 1) * 128, tid, neg1);

        // ---- MMA on current buffer ----
        float acc[8][4];
#pragma unroll
        for (int f = 0; f < 8; f++)
#pragma unroll
            for (int r = 0; r < 4; r++) acc[f][r] = 0.f;

        const uint32_t bBuf = sb + (uint32_t)((t & 1) * BBUF_SZ) + bOff;
#pragma unroll
        for (int pass = 0; pass < 3; pass++) {
            const uint32_t aP = aAddr + ((pass == 1) ? (uint32_t)(SM_AL - SM_AH) : 0u);
            const uint32_t bP = bBuf + ((pass == 2) ? (uint32_t)BLO_OFF : 0u);
#pragma unroll
            for (int kk = 0; kk < 4; kk++) {
                uint32_t a0, a1, a2, a3;
                ldm_x4(a0, a1, a2, a3, aP + kk * 32);
#pragma unroll
                for (int g = 0; g < 4; g++) {
                    uint32_t b0, b1, b2, b3;
                    ldm_x4t(b0, b1, b2, b3, bP + kk * (16 * BSTR) + g * 32);
                    mma_bf16(acc[2 * g],     a0, a1, a2, a3, b0, b1);
                    mma_bf16(acc[2 * g + 1], a0, a1, a2, a3, b2, b3);
                }
            }
        }

        // ---- epilogue for tile t ----
        {
            const int px0 = pxg + t * 128;
            if (m0 < 64) {
                const size_t ebaseV = ((size_t)(b * En + e) * Cn) * HWn + px0 + n0 + pe;
                float* p0 = g_value + ebaseV + (size_t)ch0 * HWn;
                float* p1 = g_value + ebaseV + (size_t)ch1 * HWn;
#pragma unroll
                for (int f = 0; f < 8; f++) {
                    *(float2*)(p0 + f * 8) =
                        make_float2(acc[f][0] + bia0, acc[f][1] + bia0);
                    *(float2*)(p1 + f * 8) =
                        make_float2(acc[f][2] + bia1, acc[f][3] + bia1);
                }
            } else {
                const int ck0 = ch0 - 64;             // 0..127 (K then Q)
                const int ck1 = ch1 - 64;
                const size_t kqb = (size_t)(b * 128) * En * HWn + (size_t)e * HWn
                                   + px0 + n0 + pe;
                uint32_t* q0 = g_KQ + kqb + (size_t)ck0 * (En * HWn);
                uint32_t* q1 = g_KQ + kqb + (size_t)ck1 * (En * HWn);
#pragma unroll
                for (int f = 0; f < 8; f++) {
                    uint2 s0 = packhl2(selu_f(acc[f][0] + bia0),
                                       selu_f(acc[f][1] + bia0), neg1);
                    uint2 s1 = packhl2(selu_f(acc[f][2] + bia1),
                                       selu_f(acc[f][3] + bia1), neg1);
                    *(uint2*)(q0 + f * 8) = s0;
                    *(uint2*)(q1 + f * 8) = s1;
                }
            }
        }
        __syncthreads();   // staged t+1 complete AND buf t free before next iter
    }
}

// ---------------- kernel B: gram via tensor cores ----------
// Per block (b,c): dots[i,j] = sum_px K[i,px]*Q[j,px].  GEMM M=16, N=16, K=4096.
#define GPX  256               // px per chunk
#define GSTR 264               // bf16 per smem row (528 B)
#define PLW  (16 * GSTR / 2)   // uint32 per plane = 2112

__global__ __launch_bounds__(256) void gram_kernel() {
    __shared__ __align__(16) uint32_t sp[4 * PLW];   // planes: Kh,Kl,Qh,Ql (33792 B)
    __shared__ float sred[8][256];
    const int tid = threadIdx.x;
    const int w = tid >> 5;
    const int lane = tid & 31;
    const int b = blockIdx.x >> 6;
    const int c = blockIdx.x & 63;
    const uint32_t sb = smem_u32(sp);

    const size_t kbase = ((size_t)(b * 128 + c) * En) * HWn;
    const size_t qbase = ((size_t)(b * 128 + 64 + c) * En) * HWn;

    float acc[2][4];
#pragma unroll
    for (int jt = 0; jt < 2; jt++)
#pragma unroll
        for (int r = 0; r < 4; r++) acc[jt][r] = 0.f;

    const uint32_t a_off = (uint32_t)((lane & 15) * (GSTR * 2) + (lane >> 4) * 16);
    const uint32_t b_off = (uint32_t)((lane & 7) * (GSTR * 2) + ((lane >> 3) & 1) * 16);
    const uint32_t kb0 = (uint32_t)(w * 64);      // warp's 32-px slice (bytes)

    for (int ch = 0; ch < HWn / GPX; ch++) {
        __syncthreads();
#pragma unroll
        for (int z = 0; z < 8; z++) {
            int idx = tid + z * 256;          // 0..2047
            int t = idx >> 10;                // 0=K, 1=Q
            int rem = idx & 1023;
            int row = rem >> 6;               // e
            int q4 = rem & 63;                // uint4 index within 256-px row
            size_t src = (t ? qbase : kbase) + (size_t)row * HWn + ch * GPX + q4 * 4;
            uint4 v = *(const uint4*)(g_KQ + src);
            uint32_t h0 = prmt(v.x, v.y, 0x5410);
            uint32_t l0 = prmt(v.x, v.y, 0x7632);
            uint32_t h1 = prmt(v.z, v.w, 0x5410);
            uint32_t l1 = prmt(v.z, v.w, 0x7632);
            uint2* dh = (uint2*)(sp + (t * 2) * PLW) + row * (GSTR / 4) + q4;
            uint2* dl = (uint2*)(sp + (t * 2 + 1) * PLW) + row * (GSTR / 4) + q4;
            *dh = make_uint2(h0, h1);
            *dl = make_uint2(l0, l1);
        }
        __syncthreads();

        const uint32_t kh = sb;
        const uint32_t kl = sb + 1 * (PLW * 4);
        const uint32_t qh = sb + 2 * (PLW * 4);
        const uint32_t ql = sb + 3 * (PLW * 4);
#pragma unroll
        for (int kk = 0; kk < 2; kk++) {
            const uint32_t off = kb0 + kk * 32;
            uint32_t ah0, ah1, ah2, ah3, al0, al1, al2, al3;
            ldm_x4(ah0, ah1, ah2, ah3, kh + a_off + off);
            ldm_x4(al0, al1, al2, al3, kl + a_off + off);
            uint32_t bh0, bh1, bh2, bh3, bl0, bl1, bl2, bl3;
            ldm_x2(bh0, bh1, qh + b_off + off);
            ldm_x2(bh2, bh3, qh + b_off + 8 * (GSTR * 2) + off);
            ldm_x2(bl0, bl1, ql + b_off + off);
            ldm_x2(bl2, bl3, ql + b_off + 8 * (GSTR * 2) + off);
            mma_bf16(acc[0], ah0, ah1, ah2, ah3, bh0, bh1);   // hi*hi
            mma_bf16(acc[1], ah0, ah1, ah2, ah3, bh2, bh3);
            mma_bf16(acc[0], al0, al1, al2, al3, bh0, bh1);   // lo*hi
            mma_bf16(acc[1], al0, al1, al2, al3, bh2, bh3);
            mma_bf16(acc[0], ah0, ah1, ah2, ah3, bl0, bl1);   // hi*lo
            mma_bf16(acc[1], ah0, ah1, ah2, ah3, bl2, bl3);
        }
    }

    {
        const int row = lane >> 2;
        const int c0 = (lane & 3) * 2;
#pragma unroll
        for (int jt = 0; jt < 2; jt++) {
            sred[w][row * 16 + jt * 8 + c0]           = acc[jt][0];
            sred[w][row * 16 + jt * 8 + c0 + 1]       = acc[jt][1];
            sred[w][(row + 8) * 16 + jt * 8 + c0]     = acc[jt][2];
            sred[w][(row + 8) * 16 + jt * 8 + c0 + 1] = acc[jt][3];
        }
    }
    __syncthreads();
    float s = 0.f;
#pragma unroll
    for (int ww = 0; ww < 8; ww++) s += sred[ww][tid];
    g_dots[blockIdx.x * 256 + tid] = s;
}

// ---------------- kernel C: softmax + weighted mix + SELU (unchanged) -----------
__global__ __launch_bounds__(256) void apply_kernel(float* __restrict__ out) {
    __shared__ float sd[256];
    __shared__ float sw[256];
    const int tid = threadIdx.x;
    const int chunk = blockIdx.x;   // 0..7  (512 pixels each)
    const int c = blockIdx.y;
    const int b = blockIdx.z;

    sd[tid] = g_dots[b * (Cn * En * En) + c * (En * En) + tid];
    __syncthreads();

    if (tid < 16) {
        const int j = tid;
        float m = -1e30f;
#pragma unroll
        for (int i = 0; i < 16; i++) m = fmaxf(m, sd[i * 16 + j]);
        float e[16];
        float s = 0.f;
#pragma unroll
        for (int i = 0; i < 16; i++) {
            e[i] = __expf(sd[i * 16 + j] - m);
            s += e[i];
        }
        float inv = 1.f / s;
#pragma unroll
        for (int i = 0; i < 16; i++) sw[i * 16 + j] = e[i] * inv;
    }
    __syncthreads();

    const int pix = chunk * 512 + tid * 2;
    const float* vbase = g_value + ((size_t)b * En * Cn + c) * HWn + pix;
    F2U v[16];
#pragma unroll
    for (int i = 0; i < 16; i++)
        v[i].f = *(const float2*)(vbase + (size_t)i * Cn * HWn);

    float* obase = out + ((size_t)b * En * Cn + c) * HWn + pix;
    for (int j = 0; j < 16; j++) {
        unsigned long long a0 = 0ull;
#pragma unroll
        for (int i = 0; i < 16; i++)
            a0 = fma2(pack2(sw[i * 16 + j]), v[i].u, a0);
        float f0, f1;
        unpack2(a0, f0, f1);
        F2U o;
        o.f = make_float2(selu_f(f0), selu_f(f1));
        *(float2*)(obase + (size_t)j * Cn * HWn) = o.f;
    }
}

// ---------------- launcher ----------------
extern "C" void kernel_launch(void* const* d_in, const int* in_sizes, int n_in,
                              void* d_out, int out_size) {
    const float* in = (const float*)d_in[0];
    const float* Wv = (const float*)d_in[1];
    const float* bv = (const float*)d_in[2];
    const float* Wk = (const float*)d_in[3];
    const float* bk = (const float*)d_in[4];
    const float* Wq = (const float*)d_in[5];
    const float* bq = (const float*)d_in[6];
    float* out = (float*)d_out;

    cudaFuncSetAttribute(conv_tc_kernel, cudaFuncAttributeMaxDynamicSharedMemorySize,
                         SM_A_TOTAL);

    prep_kernel<<<1, 192>>>(Wv, bv, Wk, bk, Wq, bq);
    conv_tc_kernel<<<dim3(HWn / (CTILES * 128), En, Bn), 768, SM_A_TOTAL>>>(in);
    gram_kernel<<<Bn * Cn, 256>>>();
    apply_kernel<<<dim3(8, Cn, Bn), 256>>>(out);
}